// round 5
// baseline (speedup 1.0000x reference)
#include <cuda_runtime.h>
#include <cuda_bf16.h>
#include <math.h>
#include <stdint.h>

// Problem constants: B=2, T=4096, d_model=1024, H=16, d_head=64, m=64
#define T_SEQ 4096
#define DMODEL 1024
#define NBH    32      // B*H
#define NROWS  8192    // B*T
#define NSWEEP 12

// ---------------- device scratch (no runtime allocation allowed) ----------------
__device__ __align__(16) float g_Q[NROWS * DMODEL];
__device__ __align__(16) float g_K[NROWS * DMODEL];
__device__ __align__(16) float g_V[NROWS * DMODEL];
__device__ __align__(16) float g_A[NBH * T_SEQ * 64];      // A_hat  [bh][t][mi]
__device__ __align__(16) float g_S[NBH * T_SEQ * 64];      // B raw scores
__device__ __align__(16) float g_Qlm[NBH * 64 * 64];
__device__ __align__(16) float g_Klm[NBH * 64 * 64];
__device__ __align__(16) float g_BV[NBH * 64 * 64];
__device__ __align__(16) float g_CBV[NBH * 64 * 64];
__device__ __align__(16) float g_BVpart[NBH * 8 * 64 * 64];
__device__ float g_cmax[NBH * 64];
__device__ float g_csum[NBH * 64];
// bf16 hi/lo splits
__device__ __align__(16) __nv_bfloat16 g_xh[NROWS * DMODEL];
__device__ __align__(16) __nv_bfloat16 g_xl[NROWS * DMODEL];
__device__ __align__(16) __nv_bfloat16 g_wh[4][DMODEL * DMODEL];
__device__ __align__(16) __nv_bfloat16 g_wl[4][DMODEL * DMODEL];
__device__ __align__(16) __nv_bfloat16 g_ah[NROWS * DMODEL];
__device__ __align__(16) __nv_bfloat16 g_al[NROWS * DMODEL];

// =====================  helpers  =====================
__device__ __forceinline__ uint32_t smem_u32(const void* p) {
    return (uint32_t)__cvta_generic_to_shared(p);
}
__device__ __forceinline__ void cp16(uint32_t dst, const void* src) {
    asm volatile("cp.async.cg.shared.global [%0], [%1], 16;" :: "r"(dst), "l"(src));
}
__device__ __forceinline__ void ldsm_x4(uint32_t* r, uint32_t addr) {
    asm volatile("ldmatrix.sync.aligned.m8n8.x4.shared.b16 {%0,%1,%2,%3}, [%4];"
        : "=r"(r[0]), "=r"(r[1]), "=r"(r[2]), "=r"(r[3]) : "r"(addr));
}
#define MMA16816(d, a, b) \
    asm volatile("mma.sync.aligned.m16n8k16.row.col.f32.bf16.bf16.f32 " \
        "{%0,%1,%2,%3},{%4,%5,%6,%7},{%8,%9},{%0,%1,%2,%3};" \
        : "+f"((d)[0]), "+f"((d)[1]), "+f"((d)[2]), "+f"((d)[3]) \
        : "r"((a)[0]), "r"((a)[1]), "r"((a)[2]), "r"((a)[3]), \
          "r"((b)[0]), "r"((b)[1]))

// ---------------------------------------------------------------------------
// split fp32 -> bf16 (hi, lo).
// ---------------------------------------------------------------------------
__global__ void split_kernel(const float4* __restrict__ in,
                             __nv_bfloat162* __restrict__ hi,
                             __nv_bfloat162* __restrict__ lo, int n4)
{
    int i = blockIdx.x * 256 + threadIdx.x;
    if (i >= n4) return;
    float4 v = in[i];
    __nv_bfloat16 h0 = __float2bfloat16(v.x);
    __nv_bfloat16 h1 = __float2bfloat16(v.y);
    __nv_bfloat16 h2 = __float2bfloat16(v.z);
    __nv_bfloat16 h3 = __float2bfloat16(v.w);
    __nv_bfloat162 H0, H1, L0, L1;
    H0.x = h0; H0.y = h1; H1.x = h2; H1.y = h3;
    L0.x = __float2bfloat16(v.x - __bfloat162float(h0));
    L0.y = __float2bfloat16(v.y - __bfloat162float(h1));
    L1.x = __float2bfloat16(v.z - __bfloat162float(h2));
    L1.y = __float2bfloat16(v.w - __bfloat162float(h3));
    hi[2*i] = H0; hi[2*i+1] = H1;
    lo[2*i] = L0; lo[2*i+1] = L1;
}

// ---------------------------------------------------------------------------
// mma.sync NT GEMM in 3xBF16 split precision (ldmatrix fragment feed):
//   C[M,N] = Ahi*Bhi^T + Ahi*Blo^T + Alo*Bhi^T   (fp32 accumulation)
// 128x128 CTA tile, 8 warps (warp tile 32x64), K-chunks of 32,
// 3-stage cp.async pipeline. SMEM rows padded to 80B (ldmatrix conflict-free).
// ---------------------------------------------------------------------------
#define GM_ROWB  80                 // bytes per smem row (32 bf16 + 8 pad)
#define GM_TILE  (128 * GM_ROWB)    // 10240 B
#define GM_STAGE (4 * GM_TILE)      // 40960 B (AH, AL, BH, BL)
#define GM_SMEM  (3 * GM_STAGE)     // 122880 B

__global__ __launch_bounds__(256, 1) void gemm_mma_kernel(
    const __nv_bfloat16* __restrict__ Ahi, const __nv_bfloat16* __restrict__ Alo,
    const __nv_bfloat16* __restrict__ Bhi, const __nv_bfloat16* __restrict__ Blo,
    float* __restrict__ C, int M, int N, int K)
{
    extern __shared__ __align__(128) char smem[];
    const uint32_t sb = smem_u32(smem);
    const int tid = threadIdx.x;
    const int m0 = blockIdx.y * 128, n0 = blockIdx.x * 128;
    const int wid = tid >> 5, lane = tid & 31;
    const int wr = (wid & 3) * 32;   // warp m offset in tile
    const int wc = (wid >> 2) * 64;  // warp n offset in tile
    const int lrow = tid >> 2;       // 0..63 (load row, +64 for i=1)
    const int lseg = tid & 3;        // 16B segment within 64B row data

    const int nchunks = K >> 5;      // K / 32

    auto load_stage = [&](int s, int kc) {
        uint32_t st = sb + s * GM_STAGE;
#pragma unroll
        for (int i = 0; i < 2; i++) {
            int row = lrow + i * 64;
            uint32_t off = row * GM_ROWB + lseg * 16;
            const __nv_bfloat16* gA  = Ahi + (size_t)(m0 + row) * K + kc + lseg * 8;
            const __nv_bfloat16* gAl = Alo + (size_t)(m0 + row) * K + kc + lseg * 8;
            const __nv_bfloat16* gB  = Bhi + (size_t)(n0 + row) * K + kc + lseg * 8;
            const __nv_bfloat16* gBl = Blo + (size_t)(n0 + row) * K + kc + lseg * 8;
            cp16(st +             off, gA);
            cp16(st + GM_TILE   + off, gAl);
            cp16(st + 2*GM_TILE + off, gB);
            cp16(st + 3*GM_TILE + off, gBl);
        }
        asm volatile("cp.async.commit_group;" ::: "memory");
    };

    // prologue: fill 3 stages
    load_stage(0, 0);
    load_stage(1, 32);
    load_stage(2, 64);

    float acc[2][8][4];
#pragma unroll
    for (int mt = 0; mt < 2; mt++)
#pragma unroll
        for (int nt = 0; nt < 8; nt++)
#pragma unroll
            for (int q = 0; q < 4; q++) acc[mt][nt][q] = 0.f;

    // ldmatrix lane->address bases (bytes, within a tile)
    // A .x4: matrices [m0-7,k0-7][m8-15,k0-7][m0-7,k8-15][m8-15,k8-15]
    const uint32_t aBase = (uint32_t)(wr + (lane & 15)) * GM_ROWB + (uint32_t)(lane >> 4) * 16;
    // B .x4: matrices [n0-7,k0-7][n0-7,k8-15][n8-15,k0-7][n8-15,k8-15]
    const uint32_t bBase = (uint32_t)(wc + (lane & 7) + ((lane >> 4) * 8)) * GM_ROWB
                         + (uint32_t)((lane >> 3) & 1) * 16;

    const int fr = lane >> 2;        // output fragment row within 8
    const int fc = (lane & 3) * 2;   // output fragment col within 8

    for (int c = 0; c < nchunks; c++) {
        int s = c % 3;
        asm volatile("cp.async.wait_group 2;" ::: "memory");
        __syncthreads();
        uint32_t st  = sb + s * GM_STAGE;
        uint32_t tAH = st;
        uint32_t tAL = st + GM_TILE;
        uint32_t tBH = st + 2*GM_TILE;
        uint32_t tBL = st + 3*GM_TILE;

#pragma unroll
        for (int k16 = 0; k16 < 2; k16++) {
            uint32_t kb = k16 * 32;           // 16 bf16 = 32 bytes
            uint32_t aH[2][4], aL[2][4];
#pragma unroll
            for (int mt = 0; mt < 2; mt++) {
                uint32_t ao = aBase + mt * 16 * GM_ROWB + kb;
                ldsm_x4(aH[mt], tAH + ao);
                ldsm_x4(aL[mt], tAL + ao);
            }
            uint32_t bH[8][2], bL[8][2];
#pragma unroll
            for (int p = 0; p < 4; p++) {
                uint32_t bo = bBase + p * 16 * GM_ROWB + kb;
                uint32_t tH[4], tL[4];
                ldsm_x4(tH, tBH + bo);
                ldsm_x4(tL, tBL + bo);
                bH[2*p][0] = tH[0]; bH[2*p][1] = tH[1];
                bH[2*p+1][0] = tH[2]; bH[2*p+1][1] = tH[3];
                bL[2*p][0] = tL[0]; bL[2*p][1] = tL[1];
                bL[2*p+1][0] = tL[2]; bL[2*p+1][1] = tL[3];
            }
#pragma unroll
            for (int mt = 0; mt < 2; mt++)
#pragma unroll
                for (int nt = 0; nt < 8; nt++)
                    MMA16816(acc[mt][nt], aH[mt], bH[nt]);
#pragma unroll
            for (int mt = 0; mt < 2; mt++)
#pragma unroll
                for (int nt = 0; nt < 8; nt++)
                    MMA16816(acc[mt][nt], aH[mt], bL[nt]);
#pragma unroll
            for (int mt = 0; mt < 2; mt++)
#pragma unroll
                for (int nt = 0; nt < 8; nt++)
                    MMA16816(acc[mt][nt], aL[mt], bH[nt]);
        }
        __syncthreads();
        if (c + 3 < nchunks) {
            load_stage(s, (c + 3) * 32);
        } else {
            asm volatile("cp.async.commit_group;" ::: "memory");
        }
    }

    // epilogue
#pragma unroll
    for (int mt = 0; mt < 2; mt++) {
#pragma unroll
        for (int nt = 0; nt < 8; nt++) {
            int row = m0 + wr + mt*16 + fr;
            int col = n0 + wc + nt*8 + fc;
            *(float2*)(C + (size_t)row * N + col) =
                make_float2(acc[mt][nt][0], acc[mt][nt][1]);
            *(float2*)(C + (size_t)(row + 8) * N + col) =
                make_float2(acc[mt][nt][2], acc[mt][nt][3]);
        }
    }
}

// ---------------------------------------------------------------------------
// Landmarks: segment mean over 64 consecutive t.
// ---------------------------------------------------------------------------
__global__ void landmark_kernel(const float* __restrict__ Q, const float* __restrict__ K,
                                float* __restrict__ Qlm, float* __restrict__ Klm)
{
    int mi = blockIdx.x, bh = blockIdx.y;
    int b = bh >> 4, h = bh & 15;
    const float* src = blockIdx.z ? K : Q;
    float* dst = blockIdx.z ? Klm : Qlm;
    int d = threadIdx.x;
    const float* p = src + ((size_t)b * T_SEQ + mi * 64) * DMODEL + h * 64 + d;
    float s = 0.f;
#pragma unroll 8
    for (int r = 0; r < 64; r++) s += p[(size_t)r * DMODEL];
    dst[((size_t)bh * 64 + mi) * 64 + d] = s * 0.015625f;
}

// ---------------------------------------------------------------------------
// scores: out[bh][t][mi] = (X_row(t) . Ylm[mi]) / 8, optional softmax over mi.
// ---------------------------------------------------------------------------
__global__ __launch_bounds__(128) void scores_kernel(
    const float* __restrict__ X, const float* __restrict__ Ylm,
    float* __restrict__ out, int do_softmax)
{
    int bh = blockIdx.y;
    int b = bh >> 4, h = bh & 15;
    int tid = threadIdx.x;
    int t = blockIdx.x * 128 + tid;
    __shared__ float4 Ks[1024];
    __shared__ float Ssc[64 * 128];
    const float4* Ysrc = (const float4*)(Ylm + (size_t)bh * 4096);
    for (int i = tid; i < 1024; i += 128) Ks[i] = Ysrc[i];
    __syncthreads();

    const float4* xrow = (const float4*)(X + ((size_t)b * T_SEQ + t) * DMODEL + h * 64);
    float q[64];
#pragma unroll
    for (int d4 = 0; d4 < 16; d4++) {
        float4 v = xrow[d4];
        q[4*d4+0]=v.x; q[4*d4+1]=v.y; q[4*d4+2]=v.z; q[4*d4+3]=v.w;
    }
    for (int mi = 0; mi < 64; mi++) {
        float acc = 0.f;
#pragma unroll
        for (int d4 = 0; d4 < 16; d4++) {
            float4 k4 = Ks[mi*16 + d4];
            acc = fmaf(q[4*d4+0], k4.x, acc);
            acc = fmaf(q[4*d4+1], k4.y, acc);
            acc = fmaf(q[4*d4+2], k4.z, acc);
            acc = fmaf(q[4*d4+3], k4.w, acc);
        }
        Ssc[mi*128 + tid] = acc * 0.125f;
    }
    float* orow = out + ((size_t)bh * T_SEQ + t) * 64;
    if (do_softmax) {
        float m = -INFINITY;
        for (int mi = 0; mi < 64; mi++) m = fmaxf(m, Ssc[mi*128 + tid]);
        float z = 0.f;
        for (int mi = 0; mi < 64; mi++) {
            float e = expf(Ssc[mi*128 + tid] - m);
            Ssc[mi*128 + tid] = e; z += e;
        }
        float inv = 1.0f / z;
        for (int mi = 0; mi < 64; mi += 4) {
            float4 o = make_float4(Ssc[(mi+0)*128+tid]*inv, Ssc[(mi+1)*128+tid]*inv,
                                   Ssc[(mi+2)*128+tid]*inv, Ssc[(mi+3)*128+tid]*inv);
            *(float4*)(orow + mi) = o;
        }
    } else {
        for (int mi = 0; mi < 64; mi += 4) {
            float4 o = make_float4(Ssc[(mi+0)*128+tid], Ssc[(mi+1)*128+tid],
                                   Ssc[(mi+2)*128+tid], Ssc[(mi+3)*128+tid]);
            *(float4*)(orow + mi) = o;
        }
    }
}

// ---------------------------------------------------------------------------
__global__ void colstats_kernel(const float* __restrict__ S,
                                float* __restrict__ cmax, float* __restrict__ csum)
{
    int bh = blockIdx.x;
    int tid = threadIdx.x;
    int mi = tid & 63, sub = tid >> 6;
    const float* base = S + (size_t)bh * T_SEQ * 64;
    float m = -INFINITY, z = 0.f;
    for (int t = sub; t < T_SEQ; t += 4) {
        float v = base[(size_t)t * 64 + mi];
        if (v > m) { z = z * expf(m - v) + 1.f; m = v; }
        else        z += expf(v - m);
    }
    __shared__ float sm[256], sz[256];
    sm[tid] = m; sz[tid] = z;
    __syncthreads();
    if (sub == 0) {
        for (int s2 = 1; s2 < 4; s2++) {
            float m2 = sm[s2*64 + mi], z2 = sz[s2*64 + mi];
            float nm = fmaxf(m, m2);
            z = z * expf(m - nm) + z2 * expf(m2 - nm);
            m = nm;
        }
        cmax[bh*64 + mi] = m;
        csum[bh*64 + mi] = z;
    }
}

// ---------------------------------------------------------------------------
__global__ __launch_bounds__(256) void bv_partial_kernel(
    const float* __restrict__ S, const float* __restrict__ V,
    const float* __restrict__ cmax, float* __restrict__ part)
{
    int chunk = blockIdx.x, bh = blockIdx.y;
    int b = bh >> 4, h = bh & 15;
    __shared__ float Es[64][65];
    __shared__ float Vs[64][65];
    __shared__ float cm[64];
    int tid = threadIdx.x;
    if (tid < 64) cm[tid] = cmax[bh*64 + tid];
    int ti = tid >> 4, tj = tid & 15;
    float acc[4][4] = {};
    for (int t0 = chunk*512; t0 < chunk*512 + 512; t0 += 64) {
        __syncthreads();
        for (int i = tid; i < 4096; i += 256) {
            int r = i >> 6, c = i & 63;
            Es[r][c] = expf(S[((size_t)bh*T_SEQ + t0 + r)*64 + c] - cm[c]);
            Vs[r][c] = V[((size_t)b*T_SEQ + t0 + r)*DMODEL + h*64 + c];
        }
        __syncthreads();
#pragma unroll 4
        for (int r = 0; r < 64; r++) {
            float a[4], bb[4];
#pragma unroll
            for (int x = 0; x < 4; x++) a[x]  = Es[r][ti*4+x];
#pragma unroll
            for (int y = 0; y < 4; y++) bb[y] = Vs[r][tj*4+y];
#pragma unroll
            for (int x = 0; x < 4; x++)
#pragma unroll
                for (int y = 0; y < 4; y++)
                    acc[x][y] = fmaf(a[x], bb[y], acc[x][y]);
        }
    }
    float* dst = part + ((size_t)(bh*8 + chunk)) * 4096;
#pragma unroll
    for (int x = 0; x < 4; x++)
#pragma unroll
        for (int y = 0; y < 4; y++)
            dst[(ti*4+x)*64 + tj*4+y] = acc[x][y];
}

__global__ void bv_reduce_kernel(const float* __restrict__ part,
                                 const float* __restrict__ csum, float* __restrict__ BV)
{
    int bh = blockIdx.x, tid = threadIdx.x;
    for (int i = tid; i < 4096; i += 256) {
        float s = 0.f;
#pragma unroll
        for (int ch = 0; ch < 8; ch++) s += part[((size_t)(bh*8 + ch))*4096 + i];
        BV[(size_t)bh*4096 + i] = s / csum[bh*64 + (i >> 6)];
    }
}

// ---------------------------------------------------------------------------
// pinv(C_hat) @ BV via one-sided Jacobi SVD, JAX cutoff rcond=10*64*eps.
// ---------------------------------------------------------------------------
__global__ __launch_bounds__(256) void pinv_cbv_kernel(
    const float* __restrict__ Qlm, const float* __restrict__ Klm,
    const float* __restrict__ BV, float* __restrict__ CBV)
{
    extern __shared__ float sp[];
    float* G    = sp;
    float* Vm   = sp + 4160;
    float* W    = sp + 8320;
    float* svec = sp + 12480;
    float* wvec = sp + 12544;
    int bh = blockIdx.x;
    int tid = threadIdx.x;
    int ti = tid >> 4, tj = tid & 15;

    for (int i = tid; i < 4096; i += 256) {
        int r = i >> 6, c = i & 63;
        Vm[r*65 + c] = Qlm[(size_t)bh*4096 + i];
        W [r*65 + c] = Klm[(size_t)bh*4096 + i];
    }
    __syncthreads();

    {
        float cacc[4][4] = {};
        for (int d = 0; d < 64; d++) {
            float qa[4], kb[4];
#pragma unroll
            for (int x = 0; x < 4; x++) qa[x] = Vm[(ti*4+x)*65 + d];
#pragma unroll
            for (int y = 0; y < 4; y++) kb[y] = W[(tj*4+y)*65 + d];
#pragma unroll
            for (int x = 0; x < 4; x++)
#pragma unroll
                for (int y = 0; y < 4; y++)
                    cacc[x][y] = fmaf(qa[x], kb[y], cacc[x][y]);
        }
        __syncthreads();
#pragma unroll
        for (int x = 0; x < 4; x++)
#pragma unroll
            for (int y = 0; y < 4; y++)
                G[(ti*4+x)*65 + tj*4+y] = cacc[x][y] * 0.125f;
    }
    __syncthreads();

    if (tid < 64) {
        float mx = -INFINITY;
        for (int c = 0; c < 64; c++) mx = fmaxf(mx, G[tid*65 + c]);
        float z = 0.f;
        for (int c = 0; c < 64; c++) {
            float e = expf(G[tid*65 + c] - mx);
            G[tid*65 + c] = e; z += e;
        }
        float inv = 1.f / z;
        for (int c = 0; c < 64; c++) G[tid*65 + c] *= inv;
    }
    __syncthreads();

    for (int i = tid; i < 64*65; i += 256) Vm[i] = 0.f;
    __syncthreads();
    if (tid < 64) Vm[tid*65 + tid] = 1.f;
    __syncthreads();

    {
        int p = tid >> 3, lane = tid & 7;
        for (int sw = 0; sw < NSWEEP; sw++) {
            for (int r = 0; r < 63; r++) {
                int ci, cj;
                if (p == 0) { ci = 63; cj = r; }
                else { ci = (r + p) % 63; cj = (r - p + 63) % 63; }
                float aa = 0.f, bb = 0.f, gg = 0.f;
                for (int q = lane; q < 64; q += 8) {
                    float gi = G[q*65 + ci], gj = G[q*65 + cj];
                    aa = fmaf(gi, gi, aa);
                    bb = fmaf(gj, gj, bb);
                    gg = fmaf(gi, gj, gg);
                }
#pragma unroll
                for (int o = 4; o > 0; o >>= 1) {
                    aa += __shfl_xor_sync(0xffffffffu, aa, o);
                    bb += __shfl_xor_sync(0xffffffffu, bb, o);
                    gg += __shfl_xor_sync(0xffffffffu, gg, o);
                }
                float c_ = 1.f, s_ = 0.f;
                if (fabsf(gg) > 1e-30f) {
                    float zeta = (bb - aa) / (2.0f * gg);
                    float t = copysignf(1.0f, zeta) / (fabsf(zeta) + sqrtf(1.0f + zeta*zeta));
                    c_ = 1.0f / sqrtf(1.0f + t*t);
                    s_ = c_ * t;
                }
                if (s_ != 0.f) {
                    for (int q = lane; q < 64; q += 8) {
                        float gi = G[q*65 + ci], gj = G[q*65 + cj];
                        G[q*65 + ci] = c_*gi - s_*gj;
                        G[q*65 + cj] = s_*gi + c_*gj;
                        float vi = Vm[q*65 + ci], vj = Vm[q*65 + cj];
                        Vm[q*65 + ci] = c_*vi - s_*vj;
                        Vm[q*65 + cj] = s_*vi + c_*vj;
                    }
                }
                __syncthreads();
            }
        }
    }

    if (tid < 64) {
        float ss = 0.f;
        for (int q = 0; q < 64; q++) { float g = G[q*65 + tid]; ss = fmaf(g, g, ss); }
        svec[tid] = sqrtf(ss);
    }
    __syncthreads();
    if (tid < 64) {
        float smax = 0.f;
        for (int c = 0; c < 64; c++) smax = fmaxf(smax, svec[c]);
        float cut = 7.62939453125e-5f * smax;
        float s = svec[tid];
        wvec[tid] = (s > cut) ? 1.0f / (s * s) : 0.0f;
    }
    __syncthreads();

    for (int i = tid; i < 4096; i += 256)
        W[(i >> 6)*65 + (i & 63)] = BV[(size_t)bh*4096 + i];
    __syncthreads();
    float t1[4][4] = {};
    for (int q = 0; q < 64; q++) {
        float a[4], bb[4];
#pragma unroll
        for (int x = 0; x < 4; x++) a[x]  = G[q*65 + ti*4+x];
#pragma unroll
        for (int y = 0; y < 4; y++) bb[y] = W[q*65 + tj*4+y];
#pragma unroll
        for (int x = 0; x < 4; x++)
#pragma unroll
            for (int y = 0; y < 4; y++)
                t1[x][y] = fmaf(a[x], bb[y], t1[x][y]);
    }
#pragma unroll
    for (int x = 0; x < 4; x++) {
        float w = wvec[ti*4+x];
#pragma unroll
        for (int y = 0; y < 4; y++) t1[x][y] *= w;
    }
    __syncthreads();
#pragma unroll
    for (int x = 0; x < 4; x++)
#pragma unroll
        for (int y = 0; y < 4; y++)
            G[(ti*4+x)*65 + tj*4+y] = t1[x][y];
    __syncthreads();

    float cb[4][4] = {};
    for (int q = 0; q < 64; q++) {
        float a[4], bb[4];
#pragma unroll
        for (int x = 0; x < 4; x++) a[x]  = Vm[(ti*4+x)*65 + q];
#pragma unroll
        for (int y = 0; y < 4; y++) bb[y] = G[q*65 + tj*4+y];
#pragma unroll
        for (int x = 0; x < 4; x++)
#pragma unroll
            for (int y = 0; y < 4; y++)
                cb[x][y] = fmaf(a[x], bb[y], cb[x][y]);
    }
#pragma unroll
    for (int x = 0; x < 4; x++)
#pragma unroll
        for (int y = 0; y < 4; y++)
            CBV[(size_t)bh*4096 + (ti*4+x)*64 + tj*4+y] = cb[x][y];
}

// ---------------------------------------------------------------------------
// Y = A_hat @ CBV per head -> bf16 hi/lo splits in merged-head layout.
// ---------------------------------------------------------------------------
__global__ __launch_bounds__(256) void av_kernel(
    const float* __restrict__ Ahat, const float* __restrict__ CBV,
    __nv_bfloat16* __restrict__ ahp, __nv_bfloat16* __restrict__ alp)
{
    int bh = blockIdx.y;
    int b = bh >> 4, hh = bh & 15;
    int t0 = blockIdx.x * 64;
    __shared__ float As[64*65];
    __shared__ float Cs[64*65];
    int tid = threadIdx.x;
    for (int i = tid; i < 4096; i += 256) {
        int tl = i >> 6, c = i & 63;
        As[c*65 + tl] = Ahat[((size_t)bh*T_SEQ + t0 + tl)*64 + c];
        Cs[tl*65 + c] = CBV[(size_t)bh*4096 + i];
    }
    __syncthreads();
    int ti = tid >> 4, tj = tid & 15;
    float acc[4][4] = {};
    for (int c = 0; c < 64; c++) {
        float a[4], bb[4];
#pragma unroll
        for (int x = 0; x < 4; x++) a[x]  = As[c*65 + ti*4+x];
#pragma unroll
        for (int y = 0; y < 4; y++) bb[y] = Cs[c*65 + tj*4+y];
#pragma unroll
        for (int x = 0; x < 4; x++)
#pragma unroll
            for (int y = 0; y < 4; y++)
                acc[x][y] = fmaf(a[x], bb[y], acc[x][y]);
    }
#pragma unroll
    for (int x = 0; x < 4; x++) {
        size_t idx = ((size_t)b*T_SEQ + t0 + ti*4 + x)*DMODEL + hh*64 + tj*4;
#pragma unroll
        for (int y = 0; y < 4; y += 2) {
            float v0 = acc[x][y], v1 = acc[x][y+1];
            __nv_bfloat16 h0 = __float2bfloat16(v0);
            __nv_bfloat16 h1 = __float2bfloat16(v1);
            __nv_bfloat162 Hp, Lp;
            Hp.x = h0; Hp.y = h1;
            Lp.x = __float2bfloat16(v0 - __bfloat162float(h0));
            Lp.y = __float2bfloat16(v1 - __bfloat162float(h1));
            *(__nv_bfloat162*)(ahp + idx + y) = Hp;
            *(__nv_bfloat162*)(alp + idx + y) = Lp;
        }
    }
}

// ---------------------------------------------------------------------------
extern "C" void kernel_launch(void* const* d_in, const int* in_sizes, int n_in,
                              void* d_out, int out_size)
{
    (void)in_sizes; (void)n_in; (void)out_size;
    const float* x = (const float*)d_in[0];
    const float* Wmat[4] = { (const float*)d_in[1], (const float*)d_in[2],
                             (const float*)d_in[3], (const float*)d_in[4] };
    float* out = (float*)d_out;

    float *Q, *K, *V, *A, *S, *Qlm, *Klm, *BV, *CBV, *BVp, *cmax, *csum;
    __nv_bfloat16 *xh, *xl, *wh, *wl, *ah, *al;
    cudaGetSymbolAddress((void**)&Q,    g_Q);
    cudaGetSymbolAddress((void**)&K,    g_K);
    cudaGetSymbolAddress((void**)&V,    g_V);
    cudaGetSymbolAddress((void**)&A,    g_A);
    cudaGetSymbolAddress((void**)&S,    g_S);
    cudaGetSymbolAddress((void**)&Qlm,  g_Qlm);
    cudaGetSymbolAddress((void**)&Klm,  g_Klm);
    cudaGetSymbolAddress((void**)&BV,   g_BV);
    cudaGetSymbolAddress((void**)&CBV,  g_CBV);
    cudaGetSymbolAddress((void**)&BVp,  g_BVpart);
    cudaGetSymbolAddress((void**)&cmax, g_cmax);
    cudaGetSymbolAddress((void**)&csum, g_csum);
    cudaGetSymbolAddress((void**)&xh,   g_xh);
    cudaGetSymbolAddress((void**)&xl,   g_xl);
    cudaGetSymbolAddress((void**)&wh,   g_wh);
    cudaGetSymbolAddress((void**)&wl,   g_wl);
    cudaGetSymbolAddress((void**)&ah,   g_ah);
    cudaGetSymbolAddress((void**)&al,   g_al);

    cudaFuncSetAttribute(pinv_cbv_kernel,
                         cudaFuncAttributeMaxDynamicSharedMemorySize, 50432);
    cudaFuncSetAttribute(gemm_mma_kernel,
                         cudaFuncAttributeMaxDynamicSharedMemorySize, GM_SMEM);

    // splits
    split_kernel<<<NROWS*DMODEL/4/256, 256>>>((const float4*)x,
        (__nv_bfloat162*)xh, (__nv_bfloat162*)xl, NROWS*DMODEL/4);
    for (int w = 0; w < 4; w++) {
        split_kernel<<<DMODEL*DMODEL/4/256, 256>>>((const float4*)Wmat[w],
            (__nv_bfloat162*)(wh + (size_t)w*DMODEL*DMODEL),
            (__nv_bfloat162*)(wl + (size_t)w*DMODEL*DMODEL), DMODEL*DMODEL/4);
    }

    dim3 gg(DMODEL/128, NROWS/128);   // (8, 64)
    gemm_mma_kernel<<<gg, 256, GM_SMEM>>>(xh, xl, wh + 0*(size_t)DMODEL*DMODEL,
                                          wl + 0*(size_t)DMODEL*DMODEL, Q, NROWS, DMODEL, DMODEL);
    gemm_mma_kernel<<<gg, 256, GM_SMEM>>>(xh, xl, wh + 1*(size_t)DMODEL*DMODEL,
                                          wl + 1*(size_t)DMODEL*DMODEL, K, NROWS, DMODEL, DMODEL);
    gemm_mma_kernel<<<gg, 256, GM_SMEM>>>(xh, xl, wh + 2*(size_t)DMODEL*DMODEL,
                                          wl + 2*(size_t)DMODEL*DMODEL, V, NROWS, DMODEL, DMODEL);

    landmark_kernel<<<dim3(64, NBH, 2), 64>>>(Q, K, Qlm, Klm);
    scores_kernel<<<dim3(T_SEQ/128, NBH), 128>>>(Q, Klm, A, 1);
    scores_kernel<<<dim3(T_SEQ/128, NBH), 128>>>(K, Qlm, S, 0);
    colstats_kernel<<<NBH, 256>>>(S, cmax, csum);
    bv_partial_kernel<<<dim3(8, NBH), 256>>>(S, V, cmax, BVp);
    bv_reduce_kernel<<<NBH, 256>>>(BVp, csum, BV);
    pinv_cbv_kernel<<<NBH, 256, 50432>>>(Qlm, Klm, BV, CBV);
    av_kernel<<<dim3(T_SEQ/64, NBH), 256>>>(A, CBV, ah, al);

    gemm_mma_kernel<<<gg, 256, GM_SMEM>>>(ah, al, wh + 3*(size_t)DMODEL*DMODEL,
                                          wl + 3*(size_t)DMODEL*DMODEL, out, NROWS, DMODEL, DMODEL);
}

// round 6
// speedup vs baseline: 1.0433x; 1.0433x over previous
#include <cuda_runtime.h>
#include <cuda_bf16.h>
#include <math.h>
#include <stdint.h>

// Problem constants: B=2, T=4096, d_model=1024, H=16, d_head=64, m=64
#define T_SEQ 4096
#define DMODEL 1024
#define NBH    32      // B*H
#define NROWS  8192    // B*T
#define NSWEEP 12

// ---------------- device scratch (no runtime allocation allowed) ----------------
__device__ __align__(16) float g_QKV[3 * NROWS * DMODEL];   // Q | K | V
__device__ __align__(16) float g_A[NBH * T_SEQ * 64];       // A_hat  [bh][t][mi]
__device__ __align__(16) float g_S[NBH * T_SEQ * 64];       // B raw scores
__device__ __align__(16) float g_Qlm[NBH * 64 * 64];
__device__ __align__(16) float g_Klm[NBH * 64 * 64];
__device__ __align__(16) float g_BV[NBH * 64 * 64];
__device__ __align__(16) float g_CBV[NBH * 64 * 64];
__device__ __align__(16) float g_BVpart[NBH * 8 * 64 * 64];
__device__ float g_cmax[NBH * 64];
__device__ float g_csum[NBH * 64];
// bf16 hi/lo splits
__device__ __align__(16) __nv_bfloat16 g_xh[NROWS * DMODEL];
__device__ __align__(16) __nv_bfloat16 g_xl[NROWS * DMODEL];
__device__ __align__(16) __nv_bfloat16 g_wh[4][DMODEL * DMODEL];
__device__ __align__(16) __nv_bfloat16 g_wl[4][DMODEL * DMODEL];
__device__ __align__(16) __nv_bfloat16 g_ah[NROWS * DMODEL];
__device__ __align__(16) __nv_bfloat16 g_al[NROWS * DMODEL];

// =====================  helpers  =====================
__device__ __forceinline__ uint32_t smem_u32(const void* p) {
    return (uint32_t)__cvta_generic_to_shared(p);
}
__device__ __forceinline__ void cp16(uint32_t dst, const void* src) {
    asm volatile("cp.async.cg.shared.global [%0], [%1], 16;" :: "r"(dst), "l"(src));
}
__device__ __forceinline__ void ldsm_x4(uint32_t* r, uint32_t addr) {
    asm volatile("ldmatrix.sync.aligned.m8n8.x4.shared.b16 {%0,%1,%2,%3}, [%4];"
        : "=r"(r[0]), "=r"(r[1]), "=r"(r[2]), "=r"(r[3]) : "r"(addr));
}
#define MMA16816(d, a, b) \
    asm volatile("mma.sync.aligned.m16n8k16.row.col.f32.bf16.bf16.f32 " \
        "{%0,%1,%2,%3},{%4,%5,%6,%7},{%8,%9},{%0,%1,%2,%3};" \
        : "+f"((d)[0]), "+f"((d)[1]), "+f"((d)[2]), "+f"((d)[3]) \
        : "r"((a)[0]), "r"((a)[1]), "r"((a)[2]), "r"((a)[3]), \
          "r"((b)[0]), "r"((b)[1]))

// ---------------------------------------------------------------------------
// split fp32 -> bf16 (hi, lo).
// ---------------------------------------------------------------------------
__global__ void split_kernel(const float4* __restrict__ in,
                             __nv_bfloat162* __restrict__ hi,
                             __nv_bfloat162* __restrict__ lo, int n4)
{
    int i = blockIdx.x * 256 + threadIdx.x;
    if (i >= n4) return;
    float4 v = in[i];
    __nv_bfloat16 h0 = __float2bfloat16(v.x);
    __nv_bfloat16 h1 = __float2bfloat16(v.y);
    __nv_bfloat16 h2 = __float2bfloat16(v.z);
    __nv_bfloat16 h3 = __float2bfloat16(v.w);
    __nv_bfloat162 H0, H1, L0, L1;
    H0.x = h0; H0.y = h1; H1.x = h2; H1.y = h3;
    L0.x = __float2bfloat16(v.x - __bfloat162float(h0));
    L0.y = __float2bfloat16(v.y - __bfloat162float(h1));
    L1.x = __float2bfloat16(v.z - __bfloat162float(h2));
    L1.y = __float2bfloat16(v.w - __bfloat162float(h3));
    hi[2*i] = H0; hi[2*i+1] = H1;
    lo[2*i] = L0; lo[2*i+1] = L1;
}

// ---------------------------------------------------------------------------
// mma.sync NT GEMM in 3xBF16 split precision:
//   C = Ahi*Bhi^T + Ahi*Blo^T + Alo*Bhi^T   (fp32 accumulation)
// 256x128 CTA tile, 8 warps (warp tile 64x64), K-chunks of 32,
// 3-stage cp.async pipeline, ldmatrix feed. blockIdx.z selects B/C slice
// (QKV fusion): B += z*wstride, C += z*cstride.
// ---------------------------------------------------------------------------
#define GM_ROWB  80                  // bytes per smem row (32 bf16 + 8 pad)
#define GM_TA    (256 * GM_ROWB)     // 20480 B (A tile, one of hi/lo)
#define GM_TB    (128 * GM_ROWB)     // 10240 B
#define GM_STAGE (2*GM_TA + 2*GM_TB) // 61440 B
#define GM_SMEM  (3 * GM_STAGE)      // 184320 B

__global__ __launch_bounds__(256, 1) void gemm_mma_kernel(
    const __nv_bfloat16* __restrict__ Ahi, const __nv_bfloat16* __restrict__ Alo,
    const __nv_bfloat16* __restrict__ Bhi_base, const __nv_bfloat16* __restrict__ Blo_base,
    float* __restrict__ C_base, int M, int N, int K,
    size_t wstride, size_t cstride)
{
    extern __shared__ __align__(128) char smem[];
    const uint32_t sb = smem_u32(smem);
    const int tid = threadIdx.x;
    const int z = blockIdx.z;
    const __nv_bfloat16* Bhi = Bhi_base + (size_t)z * wstride;
    const __nv_bfloat16* Blo = Blo_base + (size_t)z * wstride;
    float* C = C_base + (size_t)z * cstride;

    const int m0 = blockIdx.y * 256, n0 = blockIdx.x * 128;
    const int wid = tid >> 5, lane = tid & 31;
    const int wr = (wid & 3) * 64;   // warp m offset (4 warps over 256)
    const int wc = (wid >> 2) * 64;  // warp n offset (2 warps over 128)
    const int lrow = tid >> 2;       // 0..63
    const int lseg = tid & 3;        // 16B segment

    const int nchunks = K >> 5;      // K/32

    auto load_stage = [&](int s, int kc) {
        uint32_t st = sb + s * GM_STAGE;
        const __nv_bfloat16* gofs;
#pragma unroll
        for (int i = 0; i < 4; i++) {
            int row = lrow + i * 64;
            uint32_t off = row * GM_ROWB + lseg * 16;
            gofs = Ahi + (size_t)(m0 + row) * K + kc + lseg * 8;
            cp16(st + off, gofs);
            gofs = Alo + (size_t)(m0 + row) * K + kc + lseg * 8;
            cp16(st + GM_TA + off, gofs);
        }
#pragma unroll
        for (int i = 0; i < 2; i++) {
            int row = lrow + i * 64;
            uint32_t off = row * GM_ROWB + lseg * 16;
            gofs = Bhi + (size_t)(n0 + row) * K + kc + lseg * 8;
            cp16(st + 2*GM_TA + off, gofs);
            gofs = Blo + (size_t)(n0 + row) * K + kc + lseg * 8;
            cp16(st + 2*GM_TA + GM_TB + off, gofs);
        }
        asm volatile("cp.async.commit_group;" ::: "memory");
    };

    load_stage(0, 0);
    load_stage(1, 32);
    load_stage(2, 64);

    float acc[4][8][4];
#pragma unroll
    for (int mt = 0; mt < 4; mt++)
#pragma unroll
        for (int nt = 0; nt < 8; nt++)
#pragma unroll
            for (int q = 0; q < 4; q++) acc[mt][nt][q] = 0.f;

    // ldmatrix lane->address bases (bytes within a tile)
    const uint32_t aBase = (uint32_t)(wr + (lane & 15)) * GM_ROWB + (uint32_t)(lane >> 4) * 16;
    const uint32_t bBase = (uint32_t)(wc + (lane & 7) + ((lane >> 4) * 8)) * GM_ROWB
                         + (uint32_t)((lane >> 3) & 1) * 16;

    const int fr = lane >> 2;
    const int fc = (lane & 3) * 2;

    for (int c = 0; c < nchunks; c++) {
        int s = c % 3;
        asm volatile("cp.async.wait_group 2;" ::: "memory");
        __syncthreads();
        uint32_t st  = sb + s * GM_STAGE;
        uint32_t tAH = st;
        uint32_t tAL = st + GM_TA;
        uint32_t tBH = st + 2*GM_TA;
        uint32_t tBL = st + 2*GM_TA + GM_TB;

#pragma unroll
        for (int k16 = 0; k16 < 2; k16++) {
            uint32_t kb = k16 * 32;
            uint32_t bH[8][2], bL[8][2];
#pragma unroll
            for (int p = 0; p < 4; p++) {
                uint32_t bo = bBase + p * 16 * GM_ROWB + kb;
                uint32_t tH[4], tL[4];
                ldsm_x4(tH, tBH + bo);
                ldsm_x4(tL, tBL + bo);
                bH[2*p][0] = tH[0]; bH[2*p][1] = tH[1];
                bH[2*p+1][0] = tH[2]; bH[2*p+1][1] = tH[3];
                bL[2*p][0] = tL[0]; bL[2*p][1] = tL[1];
                bL[2*p+1][0] = tL[2]; bL[2*p+1][1] = tL[3];
            }
#pragma unroll
            for (int mt = 0; mt < 4; mt++) {
                uint32_t aH[4], aL[4];
                uint32_t ao = aBase + mt * 16 * GM_ROWB + kb;
                ldsm_x4(aH, tAH + ao);
                ldsm_x4(aL, tAL + ao);
#pragma unroll
                for (int nt = 0; nt < 8; nt++)
                    MMA16816(acc[mt][nt], aH, bH[nt]);
#pragma unroll
                for (int nt = 0; nt < 8; nt++)
                    MMA16816(acc[mt][nt], aH, bL[nt]);
#pragma unroll
                for (int nt = 0; nt < 8; nt++)
                    MMA16816(acc[mt][nt], aL, bH[nt]);
            }
        }
        __syncthreads();
        if (c + 3 < nchunks) {
            load_stage(s, (c + 3) * 32);
        } else {
            asm volatile("cp.async.commit_group;" ::: "memory");
        }
    }

    // epilogue
#pragma unroll
    for (int mt = 0; mt < 4; mt++) {
#pragma unroll
        for (int nt = 0; nt < 8; nt++) {
            int row = m0 + wr + mt*16 + fr;
            int col = n0 + wc + nt*8 + fc;
            *(float2*)(C + (size_t)row * N + col) =
                make_float2(acc[mt][nt][0], acc[mt][nt][1]);
            *(float2*)(C + (size_t)(row + 8) * N + col) =
                make_float2(acc[mt][nt][2], acc[mt][nt][3]);
        }
    }
}

// ---------------------------------------------------------------------------
// Landmarks: segment mean over 64 consecutive t.
// ---------------------------------------------------------------------------
__global__ void landmark_kernel(const float* __restrict__ Q, const float* __restrict__ K,
                                float* __restrict__ Qlm, float* __restrict__ Klm)
{
    int mi = blockIdx.x, bh = blockIdx.y;
    int b = bh >> 4, h = bh & 15;
    const float* src = blockIdx.z ? K : Q;
    float* dst = blockIdx.z ? Klm : Qlm;
    int d = threadIdx.x;
    const float* p = src + ((size_t)b * T_SEQ + mi * 64) * DMODEL + h * 64 + d;
    float s = 0.f;
#pragma unroll 8
    for (int r = 0; r < 64; r++) s += p[(size_t)r * DMODEL];
    dst[((size_t)bh * 64 + mi) * 64 + d] = s * 0.015625f;
}

// ---------------------------------------------------------------------------
// scores: out[bh][t][mi] = (X_row(t) . Ylm[mi]) / 8, optional softmax over mi.
// ---------------------------------------------------------------------------
__global__ __launch_bounds__(128) void scores_kernel(
    const float* __restrict__ X, const float* __restrict__ Ylm,
    float* __restrict__ out, int do_softmax)
{
    int bh = blockIdx.y;
    int b = bh >> 4, h = bh & 15;
    int tid = threadIdx.x;
    int t = blockIdx.x * 128 + tid;
    __shared__ float4 Ks[1024];
    __shared__ float Ssc[64 * 128];
    const float4* Ysrc = (const float4*)(Ylm + (size_t)bh * 4096);
    for (int i = tid; i < 1024; i += 128) Ks[i] = Ysrc[i];
    __syncthreads();

    const float4* xrow = (const float4*)(X + ((size_t)b * T_SEQ + t) * DMODEL + h * 64);
    float q[64];
#pragma unroll
    for (int d4 = 0; d4 < 16; d4++) {
        float4 v = xrow[d4];
        q[4*d4+0]=v.x; q[4*d4+1]=v.y; q[4*d4+2]=v.z; q[4*d4+3]=v.w;
    }
    for (int mi = 0; mi < 64; mi++) {
        float acc = 0.f;
#pragma unroll
        for (int d4 = 0; d4 < 16; d4++) {
            float4 k4 = Ks[mi*16 + d4];
            acc = fmaf(q[4*d4+0], k4.x, acc);
            acc = fmaf(q[4*d4+1], k4.y, acc);
            acc = fmaf(q[4*d4+2], k4.z, acc);
            acc = fmaf(q[4*d4+3], k4.w, acc);
        }
        Ssc[mi*128 + tid] = acc * 0.125f;
    }
    float* orow = out + ((size_t)bh * T_SEQ + t) * 64;
    if (do_softmax) {
        float m = -INFINITY;
        for (int mi = 0; mi < 64; mi++) m = fmaxf(m, Ssc[mi*128 + tid]);
        float z = 0.f;
        for (int mi = 0; mi < 64; mi++) {
            float e = expf(Ssc[mi*128 + tid] - m);
            Ssc[mi*128 + tid] = e; z += e;
        }
        float inv = 1.0f / z;
        for (int mi = 0; mi < 64; mi += 4) {
            float4 o = make_float4(Ssc[(mi+0)*128+tid]*inv, Ssc[(mi+1)*128+tid]*inv,
                                   Ssc[(mi+2)*128+tid]*inv, Ssc[(mi+3)*128+tid]*inv);
            *(float4*)(orow + mi) = o;
        }
    } else {
        for (int mi = 0; mi < 64; mi += 4) {
            float4 o = make_float4(Ssc[(mi+0)*128+tid], Ssc[(mi+1)*128+tid],
                                   Ssc[(mi+2)*128+tid], Ssc[(mi+3)*128+tid]);
            *(float4*)(orow + mi) = o;
        }
    }
}

// ---------------------------------------------------------------------------
__global__ void colstats_kernel(const float* __restrict__ S,
                                float* __restrict__ cmax, float* __restrict__ csum)
{
    int bh = blockIdx.x;
    int tid = threadIdx.x;
    int mi = tid & 63, sub = tid >> 6;
    const float* base = S + (size_t)bh * T_SEQ * 64;
    float m = -INFINITY, z = 0.f;
    for (int t = sub; t < T_SEQ; t += 4) {
        float v = base[(size_t)t * 64 + mi];
        if (v > m) { z = z * expf(m - v) + 1.f; m = v; }
        else        z += expf(v - m);
    }
    __shared__ float sm[256], sz[256];
    sm[tid] = m; sz[tid] = z;
    __syncthreads();
    if (sub == 0) {
        for (int s2 = 1; s2 < 4; s2++) {
            float m2 = sm[s2*64 + mi], z2 = sz[s2*64 + mi];
            float nm = fmaxf(m, m2);
            z = z * expf(m - nm) + z2 * expf(m2 - nm);
            m = nm;
        }
        cmax[bh*64 + mi] = m;
        csum[bh*64 + mi] = z;
    }
}

// ---------------------------------------------------------------------------
__global__ __launch_bounds__(256) void bv_partial_kernel(
    const float* __restrict__ S, const float* __restrict__ V,
    const float* __restrict__ cmax, float* __restrict__ part)
{
    int chunk = blockIdx.x, bh = blockIdx.y;
    int b = bh >> 4, h = bh & 15;
    __shared__ float Es[64][65];
    __shared__ float Vs[64][65];
    __shared__ float cm[64];
    int tid = threadIdx.x;
    if (tid < 64) cm[tid] = cmax[bh*64 + tid];
    int ti = tid >> 4, tj = tid & 15;
    float acc[4][4] = {};
    for (int t0 = chunk*512; t0 < chunk*512 + 512; t0 += 64) {
        __syncthreads();
        for (int i = tid; i < 4096; i += 256) {
            int r = i >> 6, c = i & 63;
            Es[r][c] = expf(S[((size_t)bh*T_SEQ + t0 + r)*64 + c] - cm[c]);
            Vs[r][c] = V[((size_t)b*T_SEQ + t0 + r)*DMODEL + h*64 + c];
        }
        __syncthreads();
#pragma unroll 4
        for (int r = 0; r < 64; r++) {
            float a[4], bb[4];
#pragma unroll
            for (int x = 0; x < 4; x++) a[x]  = Es[r][ti*4+x];
#pragma unroll
            for (int y = 0; y < 4; y++) bb[y] = Vs[r][tj*4+y];
#pragma unroll
            for (int x = 0; x < 4; x++)
#pragma unroll
                for (int y = 0; y < 4; y++)
                    acc[x][y] = fmaf(a[x], bb[y], acc[x][y]);
        }
    }
    float* dst = part + ((size_t)(bh*8 + chunk)) * 4096;
#pragma unroll
    for (int x = 0; x < 4; x++)
#pragma unroll
        for (int y = 0; y < 4; y++)
            dst[(ti*4+x)*64 + tj*4+y] = acc[x][y];
}

__global__ void bv_reduce_kernel(const float* __restrict__ part,
                                 const float* __restrict__ csum, float* __restrict__ BV)
{
    int bh = blockIdx.x, tid = threadIdx.x;
    for (int i = tid; i < 4096; i += 256) {
        float s = 0.f;
#pragma unroll
        for (int ch = 0; ch < 8; ch++) s += part[((size_t)(bh*8 + ch))*4096 + i];
        BV[(size_t)bh*4096 + i] = s / csum[bh*64 + (i >> 6)];
    }
}

// ---------------------------------------------------------------------------
// pinv(C_hat) @ BV via one-sided Jacobi SVD, JAX cutoff rcond=10*64*eps.
// ---------------------------------------------------------------------------
__global__ __launch_bounds__(256) void pinv_cbv_kernel(
    const float* __restrict__ Qlm, const float* __restrict__ Klm,
    const float* __restrict__ BV, float* __restrict__ CBV)
{
    extern __shared__ float sp[];
    float* G    = sp;
    float* Vm   = sp + 4160;
    float* W    = sp + 8320;
    float* svec = sp + 12480;
    float* wvec = sp + 12544;
    int bh = blockIdx.x;
    int tid = threadIdx.x;
    int ti = tid >> 4, tj = tid & 15;

    for (int i = tid; i < 4096; i += 256) {
        int r = i >> 6, c = i & 63;
        Vm[r*65 + c] = Qlm[(size_t)bh*4096 + i];
        W [r*65 + c] = Klm[(size_t)bh*4096 + i];
    }
    __syncthreads();

    {
        float cacc[4][4] = {};
        for (int d = 0; d < 64; d++) {
            float qa[4], kb[4];
#pragma unroll
            for (int x = 0; x < 4; x++) qa[x] = Vm[(ti*4+x)*65 + d];
#pragma unroll
            for (int y = 0; y < 4; y++) kb[y] = W[(tj*4+y)*65 + d];
#pragma unroll
            for (int x = 0; x < 4; x++)
#pragma unroll
                for (int y = 0; y < 4; y++)
                    cacc[x][y] = fmaf(qa[x], kb[y], cacc[x][y]);
        }
        __syncthreads();
#pragma unroll
        for (int x = 0; x < 4; x++)
#pragma unroll
            for (int y = 0; y < 4; y++)
                G[(ti*4+x)*65 + tj*4+y] = cacc[x][y] * 0.125f;
    }
    __syncthreads();

    if (tid < 64) {
        float mx = -INFINITY;
        for (int c = 0; c < 64; c++) mx = fmaxf(mx, G[tid*65 + c]);
        float z = 0.f;
        for (int c = 0; c < 64; c++) {
            float e = expf(G[tid*65 + c] - mx);
            G[tid*65 + c] = e; z += e;
        }
        float inv = 1.f / z;
        for (int c = 0; c < 64; c++) G[tid*65 + c] *= inv;
    }
    __syncthreads();

    for (int i = tid; i < 64*65; i += 256) Vm[i] = 0.f;
    __syncthreads();
    if (tid < 64) Vm[tid*65 + tid] = 1.f;
    __syncthreads();

    {
        int p = tid >> 3, lane = tid & 7;
        for (int sw = 0; sw < NSWEEP; sw++) {
            for (int r = 0; r < 63; r++) {
                int ci, cj;
                if (p == 0) { ci = 63; cj = r; }
                else { ci = (r + p) % 63; cj = (r - p + 63) % 63; }
                float aa = 0.f, bb = 0.f, gg = 0.f;
                for (int q = lane; q < 64; q += 8) {
                    float gi = G[q*65 + ci], gj = G[q*65 + cj];
                    aa = fmaf(gi, gi, aa);
                    bb = fmaf(gj, gj, bb);
                    gg = fmaf(gi, gj, gg);
                }
#pragma unroll
                for (int o = 4; o > 0; o >>= 1) {
                    aa += __shfl_xor_sync(0xffffffffu, aa, o);
                    bb += __shfl_xor_sync(0xffffffffu, bb, o);
                    gg += __shfl_xor_sync(0xffffffffu, gg, o);
                }
                float c_ = 1.f, s_ = 0.f;
                if (fabsf(gg) > 1e-30f) {
                    float zeta = (bb - aa) / (2.0f * gg);
                    float t = copysignf(1.0f, zeta) / (fabsf(zeta) + sqrtf(1.0f + zeta*zeta));
                    c_ = 1.0f / sqrtf(1.0f + t*t);
                    s_ = c_ * t;
                }
                if (s_ != 0.f) {
                    for (int q = lane; q < 64; q += 8) {
                        float gi = G[q*65 + ci], gj = G[q*65 + cj];
                        G[q*65 + ci] = c_*gi - s_*gj;
                        G[q*65 + cj] = s_*gi + c_*gj;
                        float vi = Vm[q*65 + ci], vj = Vm[q*65 + cj];
                        Vm[q*65 + ci] = c_*vi - s_*vj;
                        Vm[q*65 + cj] = s_*vi + c_*vj;
                    }
                }
                __syncthreads();
            }
        }
    }

    if (tid < 64) {
        float ss = 0.f;
        for (int q = 0; q < 64; q++) { float g = G[q*65 + tid]; ss = fmaf(g, g, ss); }
        svec[tid] = sqrtf(ss);
    }
    __syncthreads();
    if (tid < 64) {
        float smax = 0.f;
        for (int c = 0; c < 64; c++) smax = fmaxf(smax, svec[c]);
        float cut = 7.62939453125e-5f * smax;
        float s = svec[tid];
        wvec[tid] = (s > cut) ? 1.0f / (s * s) : 0.0f;
    }
    __syncthreads();

    for (int i = tid; i < 4096; i += 256)
        W[(i >> 6)*65 + (i & 63)] = BV[(size_t)bh*4096 + i];
    __syncthreads();
    float t1[4][4] = {};
    for (int q = 0; q < 64; q++) {
        float a[4], bb[4];
#pragma unroll
        for (int x = 0; x < 4; x++) a[x]  = G[q*65 + ti*4+x];
#pragma unroll
        for (int y = 0; y < 4; y++) bb[y] = W[q*65 + tj*4+y];
#pragma unroll
        for (int x = 0; x < 4; x++)
#pragma unroll
            for (int y = 0; y < 4; y++)
                t1[x][y] = fmaf(a[x], bb[y], t1[x][y]);
    }
#pragma unroll
    for (int x = 0; x < 4; x++) {
        float w = wvec[ti*4+x];
#pragma unroll
        for (int y = 0; y < 4; y++) t1[x][y] *= w;
    }
    __syncthreads();
#pragma unroll
    for (int x = 0; x < 4; x++)
#pragma unroll
        for (int y = 0; y < 4; y++)
            G[(ti*4+x)*65 + tj*4+y] = t1[x][y];
    __syncthreads();

    float cb[4][4] = {};
    for (int q = 0; q < 64; q++) {
        float a[4], bb[4];
#pragma unroll
        for (int x = 0; x < 4; x++) a[x]  = Vm[(ti*4+x)*65 + q];
#pragma unroll
        for (int y = 0; y < 4; y++) bb[y] = G[q*65 + tj*4+y];
#pragma unroll
        for (int x = 0; x < 4; x++)
#pragma unroll
            for (int y = 0; y < 4; y++)
                cb[x][y] = fmaf(a[x], bb[y], cb[x][y]);
    }
#pragma unroll
    for (int x = 0; x < 4; x++)
#pragma unroll
        for (int y = 0; y < 4; y++)
            CBV[(size_t)bh*4096 + (ti*4+x)*64 + tj*4+y] = cb[x][y];
}

// ---------------------------------------------------------------------------
// Y = A_hat @ CBV per head -> bf16 hi/lo splits in merged-head layout.
// ---------------------------------------------------------------------------
__global__ __launch_bounds__(256) void av_kernel(
    const float* __restrict__ Ahat, const float* __restrict__ CBV,
    __nv_bfloat16* __restrict__ ahp, __nv_bfloat16* __restrict__ alp)
{
    int bh = blockIdx.y;
    int b = bh >> 4, hh = bh & 15;
    int t0 = blockIdx.x * 64;
    __shared__ float As[64*65];
    __shared__ float Cs[64*65];
    int tid = threadIdx.x;
    for (int i = tid; i < 4096; i += 256) {
        int tl = i >> 6, c = i & 63;
        As[c*65 + tl] = Ahat[((size_t)bh*T_SEQ + t0 + tl)*64 + c];
        Cs[tl*65 + c] = CBV[(size_t)bh*4096 + i];
    }
    __syncthreads();
    int ti = tid >> 4, tj = tid & 15;
    float acc[4][4] = {};
    for (int c = 0; c < 64; c++) {
        float a[4], bb[4];
#pragma unroll
        for (int x = 0; x < 4; x++) a[x]  = As[c*65 + ti*4+x];
#pragma unroll
        for (int y = 0; y < 4; y++) bb[y] = Cs[c*65 + tj*4+y];
#pragma unroll
        for (int x = 0; x < 4; x++)
#pragma unroll
            for (int y = 0; y < 4; y++)
                acc[x][y] = fmaf(a[x], bb[y], acc[x][y]);
    }
#pragma unroll
    for (int x = 0; x < 4; x++) {
        size_t idx = ((size_t)b*T_SEQ + t0 + ti*4 + x)*DMODEL + hh*64 + tj*4;
#pragma unroll
        for (int y = 0; y < 4; y += 2) {
            float v0 = acc[x][y], v1 = acc[x][y+1];
            __nv_bfloat16 h0 = __float2bfloat16(v0);
            __nv_bfloat16 h1 = __float2bfloat16(v1);
            __nv_bfloat162 Hp, Lp;
            Hp.x = h0; Hp.y = h1;
            Lp.x = __float2bfloat16(v0 - __bfloat162float(h0));
            Lp.y = __float2bfloat16(v1 - __bfloat162float(h1));
            *(__nv_bfloat162*)(ahp + idx + y) = Hp;
            *(__nv_bfloat162*)(alp + idx + y) = Lp;
        }
    }
}

// ---------------------------------------------------------------------------
extern "C" void kernel_launch(void* const* d_in, const int* in_sizes, int n_in,
                              void* d_out, int out_size)
{
    (void)in_sizes; (void)n_in; (void)out_size;
    const float* x = (const float*)d_in[0];
    const float* Wmat[4] = { (const float*)d_in[1], (const float*)d_in[2],
                             (const float*)d_in[3], (const float*)d_in[4] };
    float* out = (float*)d_out;

    float *QKV, *A, *S, *Qlm, *Klm, *BV, *CBV, *BVp, *cmax, *csum;
    __nv_bfloat16 *xh, *xl, *wh, *wl, *ah, *al;
    cudaGetSymbolAddress((void**)&QKV,  g_QKV);
    cudaGetSymbolAddress((void**)&A,    g_A);
    cudaGetSymbolAddress((void**)&S,    g_S);
    cudaGetSymbolAddress((void**)&Qlm,  g_Qlm);
    cudaGetSymbolAddress((void**)&Klm,  g_Klm);
    cudaGetSymbolAddress((void**)&BV,   g_BV);
    cudaGetSymbolAddress((void**)&CBV,  g_CBV);
    cudaGetSymbolAddress((void**)&BVp,  g_BVpart);
    cudaGetSymbolAddress((void**)&cmax, g_cmax);
    cudaGetSymbolAddress((void**)&csum, g_csum);
    cudaGetSymbolAddress((void**)&xh,   g_xh);
    cudaGetSymbolAddress((void**)&xl,   g_xl);
    cudaGetSymbolAddress((void**)&wh,   g_wh);
    cudaGetSymbolAddress((void**)&wl,   g_wl);
    cudaGetSymbolAddress((void**)&ah,   g_ah);
    cudaGetSymbolAddress((void**)&al,   g_al);

    float* Q = QKV;
    float* K = QKV + (size_t)NROWS * DMODEL;
    float* V = QKV + 2 * (size_t)NROWS * DMODEL;

    cudaFuncSetAttribute(pinv_cbv_kernel,
                         cudaFuncAttributeMaxDynamicSharedMemorySize, 50432);
    cudaFuncSetAttribute(gemm_mma_kernel,
                         cudaFuncAttributeMaxDynamicSharedMemorySize, GM_SMEM);

    // splits: W first (4 launches), then x, so ncu (-s 5) lands on the QKV GEMM
    for (int w = 0; w < 4; w++) {
        split_kernel<<<DMODEL*DMODEL/4/256, 256>>>((const float4*)Wmat[w],
            (__nv_bfloat162*)(wh + (size_t)w*DMODEL*DMODEL),
            (__nv_bfloat162*)(wl + (size_t)w*DMODEL*DMODEL), DMODEL*DMODEL/4);
    }
    split_kernel<<<NROWS*DMODEL/4/256, 256>>>((const float4*)x,
        (__nv_bfloat162*)xh, (__nv_bfloat162*)xl, NROWS*DMODEL/4);

    // fused Q/K/V projection: z selects weight slice and output slice
    dim3 gq(DMODEL/128, NROWS/256, 3);   // (8, 32, 3)
    gemm_mma_kernel<<<gq, 256, GM_SMEM>>>(xh, xl, wh, wl, QKV,
                                          NROWS, DMODEL, DMODEL,
                                          (size_t)DMODEL*DMODEL, (size_t)NROWS*DMODEL);

    landmark_kernel<<<dim3(64, NBH, 2), 64>>>(Q, K, Qlm, Klm);
    scores_kernel<<<dim3(T_SEQ/128, NBH), 128>>>(Q, Klm, A, 1);
    scores_kernel<<<dim3(T_SEQ/128, NBH), 128>>>(K, Qlm, S, 0);
    colstats_kernel<<<NBH, 256>>>(S, cmax, csum);
    bv_partial_kernel<<<dim3(8, NBH), 256>>>(S, V, cmax, BVp);
    bv_reduce_kernel<<<NBH, 256>>>(BVp, csum, BV);
    pinv_cbv_kernel<<<NBH, 256, 50432>>>(Qlm, Klm, BV, CBV);
    av_kernel<<<dim3(T_SEQ/64, NBH), 256>>>(A, CBV, ah, al);

    dim3 go(DMODEL/128, NROWS/256, 1);
    gemm_mma_kernel<<<go, 256, GM_SMEM>>>(ah, al,
                                          wh + 3*(size_t)DMODEL*DMODEL,
                                          wl + 3*(size_t)DMODEL*DMODEL, out,
                                          NROWS, DMODEL, DMODEL, 0, 0);
}

// round 7
// speedup vs baseline: 1.1096x; 1.0636x over previous
#include <cuda_runtime.h>
#include <cuda_fp16.h>
#include <math.h>
#include <stdint.h>

// Problem constants: B=2, T=4096, d_model=1024, H=16, d_head=64, m=64
#define T_SEQ 4096
#define DMODEL 1024
#define NBH    32      // B*H
#define NROWS  8192    // B*T
#define NSWEEP 12

// ---------------- device scratch (no runtime allocation allowed) ----------------
__device__ __align__(16) float g_QKV[3 * NROWS * DMODEL];   // Q | K | V
__device__ __align__(16) float g_A[NBH * T_SEQ * 64];       // A_hat  [bh][t][mi]
__device__ __align__(16) float g_S[NBH * T_SEQ * 64];       // exp(B scores)
__device__ __align__(16) float g_Qlm[NBH * 64 * 64];
__device__ __align__(16) float g_Klm[NBH * 64 * 64];
__device__ __align__(16) float g_BV[NBH * 64 * 64];
__device__ __align__(16) float g_CBV[NBH * 64 * 64];
__device__ __align__(16) float g_BVpart[NBH * 8 * 64 * 64];
__device__ float g_csump[NBH * 8 * 64];
// fp16 hi/lo splits
__device__ __align__(16) __half g_xh[NROWS * DMODEL];
__device__ __align__(16) __half g_xl[NROWS * DMODEL];
__device__ __align__(16) __half g_wh[4][DMODEL * DMODEL];
__device__ __align__(16) __half g_wl[4][DMODEL * DMODEL];
__device__ __align__(16) __half g_ah[NROWS * DMODEL];
__device__ __align__(16) __half g_al[NROWS * DMODEL];

// =====================  helpers  =====================
__device__ __forceinline__ uint32_t smem_u32(const void* p) {
    return (uint32_t)__cvta_generic_to_shared(p);
}
__device__ __forceinline__ void cp16(uint32_t dst, const void* src) {
    asm volatile("cp.async.cg.shared.global [%0], [%1], 16;" :: "r"(dst), "l"(src));
}
__device__ __forceinline__ void ldsm_x4(uint32_t* r, uint32_t addr) {
    asm volatile("ldmatrix.sync.aligned.m8n8.x4.shared.b16 {%0,%1,%2,%3}, [%4];"
        : "=r"(r[0]), "=r"(r[1]), "=r"(r[2]), "=r"(r[3]) : "r"(addr));
}
// fp32-accumulate fp16 mma (main term)
#define MMA16816F(d, a, b) \
    asm volatile("mma.sync.aligned.m16n8k16.row.col.f32.f16.f16.f32 " \
        "{%0,%1,%2,%3},{%4,%5,%6,%7},{%8,%9},{%0,%1,%2,%3};" \
        : "+f"((d)[0]), "+f"((d)[1]), "+f"((d)[2]), "+f"((d)[3]) \
        : "r"((a)[0]), "r"((a)[1]), "r"((a)[2]), "r"((a)[3]), \
          "r"((b)[0]), "r"((b)[1]))
// fp16-accumulate fp16 mma (cross terms)
#define MMA16816H(d, a, b) \
    asm volatile("mma.sync.aligned.m16n8k16.row.col.f16.f16.f16.f16 " \
        "{%0,%1},{%2,%3,%4,%5},{%6,%7},{%0,%1};" \
        : "+r"((d)[0]), "+r"((d)[1]) \
        : "r"((a)[0]), "r"((a)[1]), "r"((a)[2]), "r"((a)[3]), \
          "r"((b)[0]), "r"((b)[1]))

// ---------------------------------------------------------------------------
// split fp32 -> fp16 (hi, lo).
// ---------------------------------------------------------------------------
__device__ __forceinline__ void split4(float4 v, __half2* hi, __half2* lo, int i2) {
    __half h0 = __float2half(v.x), h1 = __float2half(v.y);
    __half h2 = __float2half(v.z), h3 = __float2half(v.w);
    __half2 H0, H1, L0, L1;
    H0.x = h0; H0.y = h1; H1.x = h2; H1.y = h3;
    L0.x = __float2half(v.x - __half2float(h0));
    L0.y = __float2half(v.y - __half2float(h1));
    L1.x = __float2half(v.z - __half2float(h2));
    L1.y = __float2half(v.w - __half2float(h3));
    hi[i2] = H0; hi[i2+1] = H1;
    lo[i2] = L0; lo[i2+1] = L1;
}

__global__ void xsplit_kernel(const float4* __restrict__ in,
                              __half2* __restrict__ hi, __half2* __restrict__ lo, int n4)
{
    int i = blockIdx.x * 256 + threadIdx.x;
    if (i >= n4) return;
    split4(in[i], hi, lo, 2*i);
}

// two weight matrices per launch; blockIdx.y selects
__global__ void wsplit2_kernel(const float4* __restrict__ Wa, const float4* __restrict__ Wb,
                               __half2* __restrict__ hi, __half2* __restrict__ lo)
{
    int w = blockIdx.y;
    const float4* src = w ? Wb : Wa;
    int i = blockIdx.x * 256 + threadIdx.x;               // 0..262143
    int o2 = w * (DMODEL*DMODEL/2) + 2*i;
    split4(src[i], hi, lo, o2);
}

// ---------------------------------------------------------------------------
// mma.sync NT GEMM, fp16 split:
//   C = Ah*Bh^T (f32 acc)  +  [Ah*Bl^T + Al*Bh^T] (f16 acc, added in epilogue)
// 128x128 CTA tile, 8 warps (warp tile 32x64), K-chunks of 32,
// 3-stage cp.async pipeline, ldmatrix feed. blockIdx.z: B += z*wstride, C += z*cstride.
// ---------------------------------------------------------------------------
#define GM_ROWB  80
#define GM_TILE  (128 * GM_ROWB)
#define GM_STAGE (4 * GM_TILE)
#define GM_SMEM  (3 * GM_STAGE)    // 122880

__global__ __launch_bounds__(256, 1) void gemm_mma_kernel(
    const __half* __restrict__ Ahi, const __half* __restrict__ Alo,
    const __half* __restrict__ Bhi_base, const __half* __restrict__ Blo_base,
    float* __restrict__ C_base, int M, int N, int K,
    size_t wstride, size_t cstride)
{
    extern __shared__ __align__(128) char smem[];
    const uint32_t sb = smem_u32(smem);
    const int tid = threadIdx.x;
    const int z = blockIdx.z;
    const __half* Bhi = Bhi_base + (size_t)z * wstride;
    const __half* Blo = Blo_base + (size_t)z * wstride;
    float* C = C_base + (size_t)z * cstride;

    const int m0 = blockIdx.y * 128, n0 = blockIdx.x * 128;
    const int wid = tid >> 5, lane = tid & 31;
    const int wr = (wid & 3) * 32;
    const int wc = (wid >> 2) * 64;
    const int lrow = tid >> 2;
    const int lseg = tid & 3;

    const int nchunks = K >> 5;

    auto load_stage = [&](int s, int kc) {
        uint32_t st = sb + s * GM_STAGE;
#pragma unroll
        for (int i = 0; i < 2; i++) {
            int row = lrow + i * 64;
            uint32_t off = row * GM_ROWB + lseg * 16;
            cp16(st +             off, Ahi + (size_t)(m0 + row) * K + kc + lseg * 8);
            cp16(st + GM_TILE   + off, Alo + (size_t)(m0 + row) * K + kc + lseg * 8);
            cp16(st + 2*GM_TILE + off, Bhi + (size_t)(n0 + row) * K + kc + lseg * 8);
            cp16(st + 3*GM_TILE + off, Blo + (size_t)(n0 + row) * K + kc + lseg * 8);
        }
        asm volatile("cp.async.commit_group;" ::: "memory");
    };

    load_stage(0, 0);
    load_stage(1, 32);
    load_stage(2, 64);

    float accF[2][8][4];
    uint32_t accH[2][8][2];
#pragma unroll
    for (int mt = 0; mt < 2; mt++)
#pragma unroll
        for (int nt = 0; nt < 8; nt++) {
#pragma unroll
            for (int q = 0; q < 4; q++) accF[mt][nt][q] = 0.f;
            accH[mt][nt][0] = 0u; accH[mt][nt][1] = 0u;
        }

    const uint32_t aBase = (uint32_t)(wr + (lane & 15)) * GM_ROWB + (uint32_t)(lane >> 4) * 16;
    const uint32_t bBase = (uint32_t)(wc + (lane & 7) + ((lane >> 4) * 8)) * GM_ROWB
                         + (uint32_t)((lane >> 3) & 1) * 16;

    const int fr = lane >> 2;
    const int fc = (lane & 3) * 2;

    for (int c = 0; c < nchunks; c++) {
        int s = c % 3;
        asm volatile("cp.async.wait_group 2;" ::: "memory");
        __syncthreads();
        uint32_t st  = sb + s * GM_STAGE;
        uint32_t tAH = st;
        uint32_t tAL = st + GM_TILE;
        uint32_t tBH = st + 2*GM_TILE;
        uint32_t tBL = st + 3*GM_TILE;

#pragma unroll
        for (int k16 = 0; k16 < 2; k16++) {
            uint32_t kb = k16 * 32;
            uint32_t aH[2][4], aL[2][4];
#pragma unroll
            for (int mt = 0; mt < 2; mt++) {
                uint32_t ao = aBase + mt * 16 * GM_ROWB + kb;
                ldsm_x4(aH[mt], tAH + ao);
                ldsm_x4(aL[mt], tAL + ao);
            }
            uint32_t bH[8][2], bL[8][2];
#pragma unroll
            for (int p = 0; p < 4; p++) {
                uint32_t bo = bBase + p * 16 * GM_ROWB + kb;
                uint32_t tH[4], tL[4];
                ldsm_x4(tH, tBH + bo);
                ldsm_x4(tL, tBL + bo);
                bH[2*p][0] = tH[0]; bH[2*p][1] = tH[1];
                bH[2*p+1][0] = tH[2]; bH[2*p+1][1] = tH[3];
                bL[2*p][0] = tL[0]; bL[2*p][1] = tL[1];
                bL[2*p+1][0] = tL[2]; bL[2*p+1][1] = tL[3];
            }
#pragma unroll
            for (int mt = 0; mt < 2; mt++)
#pragma unroll
                for (int nt = 0; nt < 8; nt++)
                    MMA16816F(accF[mt][nt], aH[mt], bH[nt]);
#pragma unroll
            for (int mt = 0; mt < 2; mt++)
#pragma unroll
                for (int nt = 0; nt < 8; nt++)
                    MMA16816H(accH[mt][nt], aH[mt], bL[nt]);
#pragma unroll
            for (int mt = 0; mt < 2; mt++)
#pragma unroll
                for (int nt = 0; nt < 8; nt++)
                    MMA16816H(accH[mt][nt], aL[mt], bH[nt]);
        }
        __syncthreads();
        if (c + 3 < nchunks) {
            load_stage(s, (c + 3) * 32);
        } else {
            asm volatile("cp.async.commit_group;" ::: "memory");
        }
    }

    // epilogue: main(f32) + cross(f16)
#pragma unroll
    for (int mt = 0; mt < 2; mt++) {
#pragma unroll
        for (int nt = 0; nt < 8; nt++) {
            int row = m0 + wr + mt*16 + fr;
            int col = n0 + wc + nt*8 + fc;
            __half2 x0 = *(__half2*)&accH[mt][nt][0];   // c0,c1
            __half2 x1 = *(__half2*)&accH[mt][nt][1];   // c2,c3
            *(float2*)(C + (size_t)row * N + col) = make_float2(
                accF[mt][nt][0] + __half2float(x0.x),
                accF[mt][nt][1] + __half2float(x0.y));
            *(float2*)(C + (size_t)(row + 8) * N + col) = make_float2(
                accF[mt][nt][2] + __half2float(x1.x),
                accF[mt][nt][3] + __half2float(x1.y));
        }
    }
}

// ---------------------------------------------------------------------------
// Landmarks: segment mean over 64 consecutive t.
// ---------------------------------------------------------------------------
__global__ void landmark_kernel(const float* __restrict__ Q, const float* __restrict__ K,
                                float* __restrict__ Qlm, float* __restrict__ Klm)
{
    int mi = blockIdx.x, bh = blockIdx.y;
    int b = bh >> 4, h = bh & 15;
    const float* src = blockIdx.z ? K : Q;
    float* dst = blockIdx.z ? Klm : Qlm;
    int d = threadIdx.x;
    const float* p = src + ((size_t)b * T_SEQ + mi * 64) * DMODEL + h * 64 + d;
    float s = 0.f;
#pragma unroll 8
    for (int r = 0; r < 64; r++) s += p[(size_t)r * DMODEL];
    dst[((size_t)bh * 64 + mi) * 64 + d] = s * 0.015625f;
}

// ---------------------------------------------------------------------------
// scores: s = (X_row(t) . Ylm[mi]) / 8.
// mode 1: row-softmax over mi (A_hat).  mode 0: store exp(s) (B path; logits
// are tiny ~N(0,0.016..1), exp is safe without max shift).
// ---------------------------------------------------------------------------
__global__ __launch_bounds__(128) void scores_kernel(
    const float* __restrict__ X, const float* __restrict__ Ylm,
    float* __restrict__ out, int do_softmax)
{
    int bh = blockIdx.y;
    int b = bh >> 4, h = bh & 15;
    int tid = threadIdx.x;
    int t = blockIdx.x * 128 + tid;
    __shared__ float4 Ks[1024];
    __shared__ float Ssc[64 * 128];
    const float4* Ysrc = (const float4*)(Ylm + (size_t)bh * 4096);
    for (int i = tid; i < 1024; i += 128) Ks[i] = Ysrc[i];
    __syncthreads();

    const float4* xrow = (const float4*)(X + ((size_t)b * T_SEQ + t) * DMODEL + h * 64);
    float q[64];
#pragma unroll
    for (int d4 = 0; d4 < 16; d4++) {
        float4 v = xrow[d4];
        q[4*d4+0]=v.x; q[4*d4+1]=v.y; q[4*d4+2]=v.z; q[4*d4+3]=v.w;
    }
    for (int mi = 0; mi < 64; mi++) {
        float acc = 0.f;
#pragma unroll
        for (int d4 = 0; d4 < 16; d4++) {
            float4 k4 = Ks[mi*16 + d4];
            acc = fmaf(q[4*d4+0], k4.x, acc);
            acc = fmaf(q[4*d4+1], k4.y, acc);
            acc = fmaf(q[4*d4+2], k4.z, acc);
            acc = fmaf(q[4*d4+3], k4.w, acc);
        }
        Ssc[mi*128 + tid] = acc * 0.125f;
    }
    float* orow = out + ((size_t)bh * T_SEQ + t) * 64;
    if (do_softmax) {
        float m = -INFINITY;
        for (int mi = 0; mi < 64; mi++) m = fmaxf(m, Ssc[mi*128 + tid]);
        float z = 0.f;
        for (int mi = 0; mi < 64; mi++) {
            float e = expf(Ssc[mi*128 + tid] - m);
            Ssc[mi*128 + tid] = e; z += e;
        }
        float inv = 1.0f / z;
        for (int mi = 0; mi < 64; mi += 4) {
            float4 o = make_float4(Ssc[(mi+0)*128+tid]*inv, Ssc[(mi+1)*128+tid]*inv,
                                   Ssc[(mi+2)*128+tid]*inv, Ssc[(mi+3)*128+tid]*inv);
            *(float4*)(orow + mi) = o;
        }
    } else {
        for (int mi = 0; mi < 64; mi += 4) {
            float4 o = make_float4(expf(Ssc[(mi+0)*128+tid]), expf(Ssc[(mi+1)*128+tid]),
                                   expf(Ssc[(mi+2)*128+tid]), expf(Ssc[(mi+3)*128+tid]));
            *(float4*)(orow + mi) = o;
        }
    }
}

// ---------------------------------------------------------------------------
// BV partials over 512-row chunks: part = E^T V (E = exp scores, precomputed),
// plus per-column sums of E (softmax denominator partials).
// ---------------------------------------------------------------------------
__global__ __launch_bounds__(256) void bv_partial_kernel(
    const float* __restrict__ Se, const float* __restrict__ V,
    float* __restrict__ part, float* __restrict__ csump)
{
    int chunk = blockIdx.x, bh = blockIdx.y;
    int b = bh >> 4, h = bh & 15;
    __shared__ float Es[64][65];
    __shared__ float Vs[64][65];
    __shared__ float sred[256];
    int tid = threadIdx.x;
    int ti = tid >> 4, tj = tid & 15;
    float acc[4][4] = {};
    float cs = 0.f;                 // this thread's column-sum partial (col = tid&63)
    for (int t0 = chunk*512; t0 < chunk*512 + 512; t0 += 64) {
        __syncthreads();
        for (int i = tid; i < 4096; i += 256) {
            int r = i >> 6, c = i & 63;
            float e = Se[((size_t)bh*T_SEQ + t0 + r)*64 + c];
            Es[r][c] = e;
            cs += e;
            Vs[r][c] = V[((size_t)b*T_SEQ + t0 + r)*DMODEL + h*64 + c];
        }
        __syncthreads();
#pragma unroll 4
        for (int r = 0; r < 64; r++) {
            float a[4], bb[4];
#pragma unroll
            for (int x = 0; x < 4; x++) a[x]  = Es[r][ti*4+x];
#pragma unroll
            for (int y = 0; y < 4; y++) bb[y] = Vs[r][tj*4+y];
#pragma unroll
            for (int x = 0; x < 4; x++)
#pragma unroll
                for (int y = 0; y < 4; y++)
                    acc[x][y] = fmaf(a[x], bb[y], acc[x][y]);
        }
    }
    float* dst = part + ((size_t)(bh*8 + chunk)) * 4096;
#pragma unroll
    for (int x = 0; x < 4; x++)
#pragma unroll
        for (int y = 0; y < 4; y++)
            dst[(ti*4+x)*64 + tj*4+y] = acc[x][y];
    // reduce column sums: threads tid, tid+64, tid+128, tid+192 share col tid&63
    sred[tid] = cs;
    __syncthreads();
    if (tid < 64)
        csump[(size_t)(bh*8 + chunk)*64 + tid] =
            sred[tid] + sred[tid+64] + sred[tid+128] + sred[tid+192];
}

__global__ void bv_reduce_kernel(const float* __restrict__ part,
                                 const float* __restrict__ csump, float* __restrict__ BV)
{
    int bh = blockIdx.x, tid = threadIdx.x;
    __shared__ float den[64];
    if (tid < 64) {
        float s = 0.f;
#pragma unroll
        for (int ch = 0; ch < 8; ch++) s += csump[(size_t)(bh*8 + ch)*64 + tid];
        den[tid] = 1.0f / s;
    }
    __syncthreads();
    for (int i = tid; i < 4096; i += 256) {
        float s = 0.f;
#pragma unroll
        for (int ch = 0; ch < 8; ch++) s += part[((size_t)(bh*8 + ch))*4096 + i];
        BV[(size_t)bh*4096 + i] = s * den[i >> 6];
    }
}

// ---------------------------------------------------------------------------
// pinv(C_hat) @ BV via one-sided Jacobi SVD, JAX cutoff rcond=10*64*eps.
// ---------------------------------------------------------------------------
__global__ __launch_bounds__(256) void pinv_cbv_kernel(
    const float* __restrict__ Qlm, const float* __restrict__ Klm,
    const float* __restrict__ BV, float* __restrict__ CBV)
{
    extern __shared__ float sp[];
    float* G    = sp;
    float* Vm   = sp + 4160;
    float* W    = sp + 8320;
    float* svec = sp + 12480;
    float* wvec = sp + 12544;
    int bh = blockIdx.x;
    int tid = threadIdx.x;
    int ti = tid >> 4, tj = tid & 15;

    for (int i = tid; i < 4096; i += 256) {
        int r = i >> 6, c = i & 63;
        Vm[r*65 + c] = Qlm[(size_t)bh*4096 + i];
        W [r*65 + c] = Klm[(size_t)bh*4096 + i];
    }
    __syncthreads();

    {
        float cacc[4][4] = {};
        for (int d = 0; d < 64; d++) {
            float qa[4], kb[4];
#pragma unroll
            for (int x = 0; x < 4; x++) qa[x] = Vm[(ti*4+x)*65 + d];
#pragma unroll
            for (int y = 0; y < 4; y++) kb[y] = W[(tj*4+y)*65 + d];
#pragma unroll
            for (int x = 0; x < 4; x++)
#pragma unroll
                for (int y = 0; y < 4; y++)
                    cacc[x][y] = fmaf(qa[x], kb[y], cacc[x][y]);
        }
        __syncthreads();
#pragma unroll
        for (int x = 0; x < 4; x++)
#pragma unroll
            for (int y = 0; y < 4; y++)
                G[(ti*4+x)*65 + tj*4+y] = cacc[x][y] * 0.125f;
    }
    __syncthreads();

    if (tid < 64) {
        float mx = -INFINITY;
        for (int c = 0; c < 64; c++) mx = fmaxf(mx, G[tid*65 + c]);
        float z = 0.f;
        for (int c = 0; c < 64; c++) {
            float e = expf(G[tid*65 + c] - mx);
            G[tid*65 + c] = e; z += e;
        }
        float inv = 1.f / z;
        for (int c = 0; c < 64; c++) G[tid*65 + c] *= inv;
    }
    __syncthreads();

    for (int i = tid; i < 64*65; i += 256) Vm[i] = 0.f;
    __syncthreads();
    if (tid < 64) Vm[tid*65 + tid] = 1.f;
    __syncthreads();

    {
        int p = tid >> 3, lane = tid & 7;
        for (int sw = 0; sw < NSWEEP; sw++) {
            for (int r = 0; r < 63; r++) {
                int ci, cj;
                if (p == 0) { ci = 63; cj = r; }
                else { ci = (r + p) % 63; cj = (r - p + 63) % 63; }
                float aa = 0.f, bb = 0.f, gg = 0.f;
                for (int q = lane; q < 64; q += 8) {
                    float gi = G[q*65 + ci], gj = G[q*65 + cj];
                    aa = fmaf(gi, gi, aa);
                    bb = fmaf(gj, gj, bb);
                    gg = fmaf(gi, gj, gg);
                }
#pragma unroll
                for (int o = 4; o > 0; o >>= 1) {
                    aa += __shfl_xor_sync(0xffffffffu, aa, o);
                    bb += __shfl_xor_sync(0xffffffffu, bb, o);
                    gg += __shfl_xor_sync(0xffffffffu, gg, o);
                }
                float c_ = 1.f, s_ = 0.f;
                if (fabsf(gg) > 1e-30f) {
                    float zeta = (bb - aa) / (2.0f * gg);
                    float t = copysignf(1.0f, zeta) / (fabsf(zeta) + sqrtf(1.0f + zeta*zeta));
                    c_ = 1.0f / sqrtf(1.0f + t*t);
                    s_ = c_ * t;
                }
                if (s_ != 0.f) {
                    for (int q = lane; q < 64; q += 8) {
                        float gi = G[q*65 + ci], gj = G[q*65 + cj];
                        G[q*65 + ci] = c_*gi - s_*gj;
                        G[q*65 + cj] = s_*gi + c_*gj;
                        float vi = Vm[q*65 + ci], vj = Vm[q*65 + cj];
                        Vm[q*65 + ci] = c_*vi - s_*vj;
                        Vm[q*65 + cj] = s_*vi + c_*vj;
                    }
                }
                __syncthreads();
            }
        }
    }

    if (tid < 64) {
        float ss = 0.f;
        for (int q = 0; q < 64; q++) { float g = G[q*65 + tid]; ss = fmaf(g, g, ss); }
        svec[tid] = sqrtf(ss);
    }
    __syncthreads();
    if (tid < 64) {
        float smax = 0.f;
        for (int c = 0; c < 64; c++) smax = fmaxf(smax, svec[c]);
        float cut = 7.62939453125e-5f * smax;
        float s = svec[tid];
        wvec[tid] = (s > cut) ? 1.0f / (s * s) : 0.0f;
    }
    __syncthreads();

    for (int i = tid; i < 4096; i += 256)
        W[(i >> 6)*65 + (i & 63)] = BV[(size_t)bh*4096 + i];
    __syncthreads();
    float t1[4][4] = {};
    for (int q = 0; q < 64; q++) {
        float a[4], bb[4];
#pragma unroll
        for (int x = 0; x < 4; x++) a[x]  = G[q*65 + ti*4+x];
#pragma unroll
        for (int y = 0; y < 4; y++) bb[y] = W[q*65 + tj*4+y];
#pragma unroll
        for (int x = 0; x < 4; x++)
#pragma unroll
            for (int y = 0; y < 4; y++)
                t1[x][y] = fmaf(a[x], bb[y], t1[x][y]);
    }
#pragma unroll
    for (int x = 0; x < 4; x++) {
        float w = wvec[ti*4+x];
#pragma unroll
        for (int y = 0; y < 4; y++) t1[x][y] *= w;
    }
    __syncthreads();
#pragma unroll
    for (int x = 0; x < 4; x++)
#pragma unroll
        for (int y = 0; y < 4; y++)
            G[(ti*4+x)*65 + tj*4+y] = t1[x][y];
    __syncthreads();

    float cb[4][4] = {};
    for (int q = 0; q < 64; q++) {
        float a[4], bb[4];
#pragma unroll
        for (int x = 0; x < 4; x++) a[x]  = Vm[(ti*4+x)*65 + q];
#pragma unroll
        for (int y = 0; y < 4; y++) bb[y] = G[q*65 + tj*4+y];
#pragma unroll
        for (int x = 0; x < 4; x++)
#pragma unroll
            for (int y = 0; y < 4; y++)
                cb[x][y] = fmaf(a[x], bb[y], cb[x][y]);
    }
#pragma unroll
    for (int x = 0; x < 4; x++)
#pragma unroll
        for (int y = 0; y < 4; y++)
            CBV[(size_t)bh*4096 + (ti*4+x)*64 + tj*4+y] = cb[x][y];
}

// ---------------------------------------------------------------------------
// Y = A_hat @ CBV per head -> fp16 hi/lo splits in merged-head layout.
// ---------------------------------------------------------------------------
__global__ __launch_bounds__(256) void av_kernel(
    const float* __restrict__ Ahat, const float* __restrict__ CBV,
    __half* __restrict__ ahp, __half* __restrict__ alp)
{
    int bh = blockIdx.y;
    int b = bh >> 4, hh = bh & 15;
    int t0 = blockIdx.x * 64;
    __shared__ float As[64*65];
    __shared__ float Cs[64*65];
    int tid = threadIdx.x;
    for (int i = tid; i < 4096; i += 256) {
        int tl = i >> 6, c = i & 63;
        As[c*65 + tl] = Ahat[((size_t)bh*T_SEQ + t0 + tl)*64 + c];
        Cs[tl*65 + c] = CBV[(size_t)bh*4096 + i];
    }
    __syncthreads();
    int ti = tid >> 4, tj = tid & 15;
    float acc[4][4] = {};
    for (int c = 0; c < 64; c++) {
        float a[4], bb[4];
#pragma unroll
        for (int x = 0; x < 4; x++) a[x]  = As[c*65 + ti*4+x];
#pragma unroll
        for (int y = 0; y < 4; y++) bb[y] = Cs[c*65 + tj*4+y];
#pragma unroll
        for (int x = 0; x < 4; x++)
#pragma unroll
            for (int y = 0; y < 4; y++)
                acc[x][y] = fmaf(a[x], bb[y], acc[x][y]);
    }
#pragma unroll
    for (int x = 0; x < 4; x++) {
        size_t idx = ((size_t)b*T_SEQ + t0 + ti*4 + x)*DMODEL + hh*64 + tj*4;
#pragma unroll
        for (int y = 0; y < 4; y += 2) {
            float v0 = acc[x][y], v1 = acc[x][y+1];
            __half h0 = __float2half(v0);
            __half h1 = __float2half(v1);
            __half2 Hp, Lp;
            Hp.x = h0; Hp.y = h1;
            Lp.x = __float2half(v0 - __half2float(h0));
            Lp.y = __float2half(v1 - __half2float(h1));
            *(__half2*)(ahp + idx + y) = Hp;
            *(__half2*)(alp + idx + y) = Lp;
        }
    }
}

// ---------------------------------------------------------------------------
extern "C" void kernel_launch(void* const* d_in, const int* in_sizes, int n_in,
                              void* d_out, int out_size)
{
    (void)in_sizes; (void)n_in; (void)out_size;
    const float* x = (const float*)d_in[0];
    const float* Wq = (const float*)d_in[1];
    const float* Wk = (const float*)d_in[2];
    const float* Wv = (const float*)d_in[3];
    const float* Wo = (const float*)d_in[4];
    float* out = (float*)d_out;

    float *QKV, *A, *S, *Qlm, *Klm, *BV, *CBV, *BVp, *csump;
    __half *xh, *xl, *wh, *wl, *ah, *al;
    cudaGetSymbolAddress((void**)&QKV,   g_QKV);
    cudaGetSymbolAddress((void**)&A,     g_A);
    cudaGetSymbolAddress((void**)&S,     g_S);
    cudaGetSymbolAddress((void**)&Qlm,   g_Qlm);
    cudaGetSymbolAddress((void**)&Klm,   g_Klm);
    cudaGetSymbolAddress((void**)&BV,    g_BV);
    cudaGetSymbolAddress((void**)&CBV,   g_CBV);
    cudaGetSymbolAddress((void**)&BVp,   g_BVpart);
    cudaGetSymbolAddress((void**)&csump, g_csump);
    cudaGetSymbolAddress((void**)&xh,    g_xh);
    cudaGetSymbolAddress((void**)&xl,    g_xl);
    cudaGetSymbolAddress((void**)&wh,    g_wh);
    cudaGetSymbolAddress((void**)&wl,    g_wl);
    cudaGetSymbolAddress((void**)&ah,    g_ah);
    cudaGetSymbolAddress((void**)&al,    g_al);

    float* Q = QKV;
    float* K = QKV + (size_t)NROWS * DMODEL;
    float* V = QKV + 2 * (size_t)NROWS * DMODEL;

    cudaFuncSetAttribute(pinv_cbv_kernel,
                         cudaFuncAttributeMaxDynamicSharedMemorySize, 50432);
    cudaFuncSetAttribute(gemm_mma_kernel,
                         cudaFuncAttributeMaxDynamicSharedMemorySize, GM_SMEM);

    // 4 split launches, then GEMM (aligns ncu -s 5 onto the GEMM)
    wsplit2_kernel<<<dim3(1024, 2), 256>>>((const float4*)Wq, (const float4*)Wk,
        (__half2*)wh, (__half2*)wl);
    wsplit2_kernel<<<dim3(1024, 2), 256>>>((const float4*)Wv, (const float4*)Wo,
        (__half2*)(wh + 2*(size_t)DMODEL*DMODEL), (__half2*)(wl + 2*(size_t)DMODEL*DMODEL));
    const int half4 = NROWS*DMODEL/8;    // float4 count per half
    xsplit_kernel<<<4096, 256>>>((const float4*)x, (__half2*)xh, (__half2*)xl, half4);
    xsplit_kernel<<<4096, 256>>>((const float4*)x + half4,
        (__half2*)(xh + (size_t)NROWS*DMODEL/2), (__half2*)(xl + (size_t)NROWS*DMODEL/2), half4);

    // fused Q/K/V projection
    dim3 gq(DMODEL/128, NROWS/128, 3);
    gemm_mma_kernel<<<gq, 256, GM_SMEM>>>(xh, xl, wh, wl, QKV,
                                          NROWS, DMODEL, DMODEL,
                                          (size_t)DMODEL*DMODEL, (size_t)NROWS*DMODEL);

    landmark_kernel<<<dim3(64, NBH, 2), 64>>>(Q, K, Qlm, Klm);
    scores_kernel<<<dim3(T_SEQ/128, NBH), 128>>>(Q, Klm, A, 1);
    scores_kernel<<<dim3(T_SEQ/128, NBH), 128>>>(K, Qlm, S, 0);
    bv_partial_kernel<<<dim3(8, NBH), 256>>>(S, V, BVp, csump);
    bv_reduce_kernel<<<NBH, 256>>>(BVp, csump, BV);
    pinv_cbv_kernel<<<NBH, 256, 50432>>>(Qlm, Klm, BV, CBV);
    av_kernel<<<dim3(T_SEQ/64, NBH), 256>>>(A, CBV, ah, al);

    dim3 go(DMODEL/128, NROWS/128, 1);
    gemm_mma_kernel<<<go, 256, GM_SMEM>>>(ah, al,
                                          wh + 3*(size_t)DMODEL*DMODEL,
                                          wl + 3*(size_t)DMODEL*DMODEL, out,
                                          NROWS, DMODEL, DMODEL, 0, 0);
}

// round 8
// speedup vs baseline: 1.2297x; 1.1082x over previous
#include <cuda_runtime.h>
#include <cuda_fp16.h>
#include <math.h>
#include <stdint.h>

// Problem constants: B=2, T=4096, d_model=1024, H=16, d_head=64, m=64
#define T_SEQ 4096
#define DMODEL 1024
#define NBH    32      // B*H
#define NROWS  8192    // B*T
#define NSWEEP 12

// ---------------- device scratch (no runtime allocation allowed) ----------------
__device__ __align__(16) float g_QKV[3 * NROWS * DMODEL];   // Q | K | V
__device__ __align__(16) float g_A[NBH * T_SEQ * 64];       // A_hat  [bh][t][mi]
__device__ __align__(16) float g_S[NBH * T_SEQ * 64];       // exp(B scores)
__device__ __align__(16) float g_Qlm[NBH * 64 * 64];
__device__ __align__(16) float g_Klm[NBH * 64 * 64];
__device__ __align__(16) float g_BV[NBH * 64 * 64];
__device__ __align__(16) float g_CBV[NBH * 64 * 64];
__device__ __align__(16) float g_BVpart[NBH * 8 * 64 * 64];
__device__ float g_csump[NBH * 8 * 64];
// fp16 splits: activations hi only; weights hi+lo
__device__ __align__(16) __half g_xh[NROWS * DMODEL];
__device__ __align__(16) __half g_wh[4][DMODEL * DMODEL];
__device__ __align__(16) __half g_wl[4][DMODEL * DMODEL];
__device__ __align__(16) __half g_ah[NROWS * DMODEL];

// =====================  helpers  =====================
__device__ __forceinline__ uint32_t smem_u32(const void* p) {
    return (uint32_t)__cvta_generic_to_shared(p);
}
__device__ __forceinline__ void cp16(uint32_t dst, const void* src) {
    asm volatile("cp.async.cg.shared.global [%0], [%1], 16;" :: "r"(dst), "l"(src));
}
__device__ __forceinline__ void ldsm_x4(uint32_t* r, uint32_t addr) {
    asm volatile("ldmatrix.sync.aligned.m8n8.x4.shared.b16 {%0,%1,%2,%3}, [%4];"
        : "=r"(r[0]), "=r"(r[1]), "=r"(r[2]), "=r"(r[3]) : "r"(addr));
}
#define MMA16816F(d, a, b) \
    asm volatile("mma.sync.aligned.m16n8k16.row.col.f32.f16.f16.f32 " \
        "{%0,%1,%2,%3},{%4,%5,%6,%7},{%8,%9},{%0,%1,%2,%3};" \
        : "+f"((d)[0]), "+f"((d)[1]), "+f"((d)[2]), "+f"((d)[3]) \
        : "r"((a)[0]), "r"((a)[1]), "r"((a)[2]), "r"((a)[3]), \
          "r"((b)[0]), "r"((b)[1]))

// ---------------------------------------------------------------------------
// splits
// ---------------------------------------------------------------------------
__global__ void xsplit_kernel(const float4* __restrict__ in,
                              __half2* __restrict__ hi, int n4)
{
    int i = blockIdx.x * 256 + threadIdx.x;
    if (i >= n4) return;
    float4 v = in[i];
    __half2 H0, H1;
    H0.x = __float2half(v.x); H0.y = __float2half(v.y);
    H1.x = __float2half(v.z); H1.y = __float2half(v.w);
    hi[2*i] = H0; hi[2*i+1] = H1;
}

// two weight matrices per launch; blockIdx.y selects. hi + lo.
__global__ void wsplit2_kernel(const float4* __restrict__ Wa, const float4* __restrict__ Wb,
                               __half2* __restrict__ hi, __half2* __restrict__ lo)
{
    int w = blockIdx.y;
    const float4* src = w ? Wb : Wa;
    int i = blockIdx.x * 256 + threadIdx.x;
    int o2 = w * (DMODEL*DMODEL/2) + 2*i;
    float4 v = src[i];
    __half h0 = __float2half(v.x), h1 = __float2half(v.y);
    __half h2 = __float2half(v.z), h3 = __float2half(v.w);
    __half2 H0, H1, L0, L1;
    H0.x = h0; H0.y = h1; H1.x = h2; H1.y = h3;
    L0.x = __float2half(v.x - __half2float(h0));
    L0.y = __float2half(v.y - __half2float(h1));
    L1.x = __float2half(v.z - __half2float(h2));
    L1.y = __float2half(v.w - __half2float(h3));
    hi[o2] = H0; hi[o2+1] = H1;
    lo[o2] = L0; lo[o2+1] = L1;
}

// ---------------------------------------------------------------------------
// mma.sync NT GEMM, 2-term fp16 split (weights carry the residual):
//   C = Ah*Bh^T + Ah*Bl^T   (both fp32 accumulate)
// 128x128 CTA tile, 8 warps (warp tile 32x64), K-chunks of 32,
// 3-stage cp.async pipeline, ldmatrix feed. blockIdx.z: B += z*wstride, C += z*cstride.
// ---------------------------------------------------------------------------
#define GM_ROWB  80
#define GM_TILE  (128 * GM_ROWB)      // 10240
#define GM_STAGE (3 * GM_TILE)        // 30720  (AH, BH, BL)
#define GM_SMEM  (3 * GM_STAGE)       // 92160

__global__ __launch_bounds__(256, 1) void gemm_mma_kernel(
    const __half* __restrict__ Ahi,
    const __half* __restrict__ Bhi_base, const __half* __restrict__ Blo_base,
    float* __restrict__ C_base, int M, int N, int K,
    size_t wstride, size_t cstride)
{
    extern __shared__ __align__(128) char smem[];
    const uint32_t sb = smem_u32(smem);
    const int tid = threadIdx.x;
    const int z = blockIdx.z;
    const __half* Bhi = Bhi_base + (size_t)z * wstride;
    const __half* Blo = Blo_base + (size_t)z * wstride;
    float* C = C_base + (size_t)z * cstride;

    const int m0 = blockIdx.y * 128, n0 = blockIdx.x * 128;
    const int wid = tid >> 5, lane = tid & 31;
    const int wr = (wid & 3) * 32;
    const int wc = (wid >> 2) * 64;
    const int lrow = tid >> 2;
    const int lseg = tid & 3;

    const int nchunks = K >> 5;

    auto load_stage = [&](int s, int kc) {
        uint32_t st = sb + s * GM_STAGE;
#pragma unroll
        for (int i = 0; i < 2; i++) {
            int row = lrow + i * 64;
            uint32_t off = row * GM_ROWB + lseg * 16;
            cp16(st +             off, Ahi + (size_t)(m0 + row) * K + kc + lseg * 8);
            cp16(st + GM_TILE   + off, Bhi + (size_t)(n0 + row) * K + kc + lseg * 8);
            cp16(st + 2*GM_TILE + off, Blo + (size_t)(n0 + row) * K + kc + lseg * 8);
        }
        asm volatile("cp.async.commit_group;" ::: "memory");
    };

    load_stage(0, 0);
    load_stage(1, 32);
    load_stage(2, 64);

    float accF[2][8][4];
#pragma unroll
    for (int mt = 0; mt < 2; mt++)
#pragma unroll
        for (int nt = 0; nt < 8; nt++)
#pragma unroll
            for (int q = 0; q < 4; q++) accF[mt][nt][q] = 0.f;

    const uint32_t aBase = (uint32_t)(wr + (lane & 15)) * GM_ROWB + (uint32_t)(lane >> 4) * 16;
    const uint32_t bBase = (uint32_t)(wc + (lane & 7) + ((lane >> 4) * 8)) * GM_ROWB
                         + (uint32_t)((lane >> 3) & 1) * 16;

    const int fr = lane >> 2;
    const int fc = (lane & 3) * 2;

    for (int c = 0; c < nchunks; c++) {
        int s = c % 3;
        asm volatile("cp.async.wait_group 2;" ::: "memory");
        __syncthreads();
        uint32_t st  = sb + s * GM_STAGE;
        uint32_t tAH = st;
        uint32_t tBH = st + GM_TILE;
        uint32_t tBL = st + 2*GM_TILE;

#pragma unroll
        for (int k16 = 0; k16 < 2; k16++) {
            uint32_t kb = k16 * 32;
            uint32_t aH[2][4];
#pragma unroll
            for (int mt = 0; mt < 2; mt++)
                ldsm_x4(aH[mt], tAH + aBase + mt * 16 * GM_ROWB + kb);
            uint32_t bH[8][2], bL[8][2];
#pragma unroll
            for (int p = 0; p < 4; p++) {
                uint32_t bo = bBase + p * 16 * GM_ROWB + kb;
                uint32_t tH[4], tL[4];
                ldsm_x4(tH, tBH + bo);
                ldsm_x4(tL, tBL + bo);
                bH[2*p][0] = tH[0]; bH[2*p][1] = tH[1];
                bH[2*p+1][0] = tH[2]; bH[2*p+1][1] = tH[3];
                bL[2*p][0] = tL[0]; bL[2*p][1] = tL[1];
                bL[2*p+1][0] = tL[2]; bL[2*p+1][1] = tL[3];
            }
#pragma unroll
            for (int mt = 0; mt < 2; mt++)
#pragma unroll
                for (int nt = 0; nt < 8; nt++)
                    MMA16816F(accF[mt][nt], aH[mt], bH[nt]);
#pragma unroll
            for (int mt = 0; mt < 2; mt++)
#pragma unroll
                for (int nt = 0; nt < 8; nt++)
                    MMA16816F(accF[mt][nt], aH[mt], bL[nt]);
        }
        __syncthreads();
        if (c + 3 < nchunks) {
            load_stage(s, (c + 3) * 32);
        } else {
            asm volatile("cp.async.commit_group;" ::: "memory");
        }
    }

    // epilogue
#pragma unroll
    for (int mt = 0; mt < 2; mt++) {
#pragma unroll
        for (int nt = 0; nt < 8; nt++) {
            int row = m0 + wr + mt*16 + fr;
            int col = n0 + wc + nt*8 + fc;
            *(float2*)(C + (size_t)row * N + col) =
                make_float2(accF[mt][nt][0], accF[mt][nt][1]);
            *(float2*)(C + (size_t)(row + 8) * N + col) =
                make_float2(accF[mt][nt][2], accF[mt][nt][3]);
        }
    }
}

// ---------------------------------------------------------------------------
// Landmarks: segment mean over 64 consecutive t.
// ---------------------------------------------------------------------------
__global__ void landmark_kernel(const float* __restrict__ Q, const float* __restrict__ K,
                                float* __restrict__ Qlm, float* __restrict__ Klm)
{
    int mi = blockIdx.x, bh = blockIdx.y;
    int b = bh >> 4, h = bh & 15;
    const float* src = blockIdx.z ? K : Q;
    float* dst = blockIdx.z ? Klm : Qlm;
    int d = threadIdx.x;
    const float* p = src + ((size_t)b * T_SEQ + mi * 64) * DMODEL + h * 64 + d;
    float s = 0.f;
#pragma unroll 8
    for (int r = 0; r < 64; r++) s += p[(size_t)r * DMODEL];
    dst[((size_t)bh * 64 + mi) * 64 + d] = s * 0.015625f;
}

// ---------------------------------------------------------------------------
// scores: s = (X_row(t) . Ylm[mi]) / 8.
// mode 1: row-softmax over mi (A_hat).  mode 0: store exp(s).
// ---------------------------------------------------------------------------
__global__ __launch_bounds__(128) void scores_kernel(
    const float* __restrict__ X, const float* __restrict__ Ylm,
    float* __restrict__ out, int do_softmax)
{
    int bh = blockIdx.y;
    int b = bh >> 4, h = bh & 15;
    int tid = threadIdx.x;
    int t = blockIdx.x * 128 + tid;
    __shared__ float4 Ks[1024];
    __shared__ float Ssc[64 * 128];
    const float4* Ysrc = (const float4*)(Ylm + (size_t)bh * 4096);
    for (int i = tid; i < 1024; i += 128) Ks[i] = Ysrc[i];
    __syncthreads();

    const float4* xrow = (const float4*)(X + ((size_t)b * T_SEQ + t) * DMODEL + h * 64);
    float q[64];
#pragma unroll
    for (int d4 = 0; d4 < 16; d4++) {
        float4 v = xrow[d4];
        q[4*d4+0]=v.x; q[4*d4+1]=v.y; q[4*d4+2]=v.z; q[4*d4+3]=v.w;
    }
    for (int mi = 0; mi < 64; mi++) {
        float acc = 0.f;
#pragma unroll
        for (int d4 = 0; d4 < 16; d4++) {
            float4 k4 = Ks[mi*16 + d4];
            acc = fmaf(q[4*d4+0], k4.x, acc);
            acc = fmaf(q[4*d4+1], k4.y, acc);
            acc = fmaf(q[4*d4+2], k4.z, acc);
            acc = fmaf(q[4*d4+3], k4.w, acc);
        }
        Ssc[mi*128 + tid] = acc * 0.125f;
    }
    float* orow = out + ((size_t)bh * T_SEQ + t) * 64;
    if (do_softmax) {
        float m = -INFINITY;
        for (int mi = 0; mi < 64; mi++) m = fmaxf(m, Ssc[mi*128 + tid]);
        float z = 0.f;
        for (int mi = 0; mi < 64; mi++) {
            float e = expf(Ssc[mi*128 + tid] - m);
            Ssc[mi*128 + tid] = e; z += e;
        }
        float inv = 1.0f / z;
        for (int mi = 0; mi < 64; mi += 4) {
            float4 o = make_float4(Ssc[(mi+0)*128+tid]*inv, Ssc[(mi+1)*128+tid]*inv,
                                   Ssc[(mi+2)*128+tid]*inv, Ssc[(mi+3)*128+tid]*inv);
            *(float4*)(orow + mi) = o;
        }
    } else {
        for (int mi = 0; mi < 64; mi += 4) {
            float4 o = make_float4(expf(Ssc[(mi+0)*128+tid]), expf(Ssc[(mi+1)*128+tid]),
                                   expf(Ssc[(mi+2)*128+tid]), expf(Ssc[(mi+3)*128+tid]));
            *(float4*)(orow + mi) = o;
        }
    }
}

// ---------------------------------------------------------------------------
// BV partials over 512-row chunks: part = E^T V + per-column sums of E.
// ---------------------------------------------------------------------------
__global__ __launch_bounds__(256) void bv_partial_kernel(
    const float* __restrict__ Se, const float* __restrict__ V,
    float* __restrict__ part, float* __restrict__ csump)
{
    int chunk = blockIdx.x, bh = blockIdx.y;
    int b = bh >> 4, h = bh & 15;
    __shared__ float Es[64][65];
    __shared__ float Vs[64][65];
    __shared__ float sred[256];
    int tid = threadIdx.x;
    int ti = tid >> 4, tj = tid & 15;
    float acc[4][4] = {};
    float cs = 0.f;
    for (int t0 = chunk*512; t0 < chunk*512 + 512; t0 += 64) {
        __syncthreads();
        for (int i = tid; i < 4096; i += 256) {
            int r = i >> 6, c = i & 63;
            float e = Se[((size_t)bh*T_SEQ + t0 + r)*64 + c];
            Es[r][c] = e;
            cs += e;
            Vs[r][c] = V[((size_t)b*T_SEQ + t0 + r)*DMODEL + h*64 + c];
        }
        __syncthreads();
#pragma unroll 4
        for (int r = 0; r < 64; r++) {
            float a[4], bb[4];
#pragma unroll
            for (int x = 0; x < 4; x++) a[x]  = Es[r][ti*4+x];
#pragma unroll
            for (int y = 0; y < 4; y++) bb[y] = Vs[r][tj*4+y];
#pragma unroll
            for (int x = 0; x < 4; x++)
#pragma unroll
                for (int y = 0; y < 4; y++)
                    acc[x][y] = fmaf(a[x], bb[y], acc[x][y]);
        }
    }
    float* dst = part + ((size_t)(bh*8 + chunk)) * 4096;
#pragma unroll
    for (int x = 0; x < 4; x++)
#pragma unroll
        for (int y = 0; y < 4; y++)
            dst[(ti*4+x)*64 + tj*4+y] = acc[x][y];
    sred[tid] = cs;
    __syncthreads();
    if (tid < 64)
        csump[(size_t)(bh*8 + chunk)*64 + tid] =
            sred[tid] + sred[tid+64] + sred[tid+128] + sred[tid+192];
}

__global__ void bv_reduce_kernel(const float* __restrict__ part,
                                 const float* __restrict__ csump, float* __restrict__ BV)
{
    int bh = blockIdx.x, tid = threadIdx.x;
    __shared__ float den[64];
    if (tid < 64) {
        float s = 0.f;
#pragma unroll
        for (int ch = 0; ch < 8; ch++) s += csump[(size_t)(bh*8 + ch)*64 + tid];
        den[tid] = 1.0f / s;
    }
    __syncthreads();
    for (int i = tid; i < 4096; i += 256) {
        float s = 0.f;
#pragma unroll
        for (int ch = 0; ch < 8; ch++) s += part[((size_t)(bh*8 + ch))*4096 + i];
        BV[(size_t)bh*4096 + i] = s * den[i >> 6];
    }
}

// ---------------------------------------------------------------------------
// pinv(C_hat) @ BV via one-sided Jacobi SVD, JAX cutoff rcond=10*64*eps.
// ---------------------------------------------------------------------------
__global__ __launch_bounds__(256) void pinv_cbv_kernel(
    const float* __restrict__ Qlm, const float* __restrict__ Klm,
    const float* __restrict__ BV, float* __restrict__ CBV)
{
    extern __shared__ float sp[];
    float* G    = sp;
    float* Vm   = sp + 4160;
    float* W    = sp + 8320;
    float* svec = sp + 12480;
    float* wvec = sp + 12544;
    int bh = blockIdx.x;
    int tid = threadIdx.x;
    int ti = tid >> 4, tj = tid & 15;

    for (int i = tid; i < 4096; i += 256) {
        int r = i >> 6, c = i & 63;
        Vm[r*65 + c] = Qlm[(size_t)bh*4096 + i];
        W [r*65 + c] = Klm[(size_t)bh*4096 + i];
    }
    __syncthreads();

    {
        float cacc[4][4] = {};
        for (int d = 0; d < 64; d++) {
            float qa[4], kb[4];
#pragma unroll
            for (int x = 0; x < 4; x++) qa[x] = Vm[(ti*4+x)*65 + d];
#pragma unroll
            for (int y = 0; y < 4; y++) kb[y] = W[(tj*4+y)*65 + d];
#pragma unroll
            for (int x = 0; x < 4; x++)
#pragma unroll
                for (int y = 0; y < 4; y++)
                    cacc[x][y] = fmaf(qa[x], kb[y], cacc[x][y]);
        }
        __syncthreads();
#pragma unroll
        for (int x = 0; x < 4; x++)
#pragma unroll
            for (int y = 0; y < 4; y++)
                G[(ti*4+x)*65 + tj*4+y] = cacc[x][y] * 0.125f;
    }
    __syncthreads();

    if (tid < 64) {
        float mx = -INFINITY;
        for (int c = 0; c < 64; c++) mx = fmaxf(mx, G[tid*65 + c]);
        float z = 0.f;
        for (int c = 0; c < 64; c++) {
            float e = expf(G[tid*65 + c] - mx);
            G[tid*65 + c] = e; z += e;
        }
        float inv = 1.f / z;
        for (int c = 0; c < 64; c++) G[tid*65 + c] *= inv;
    }
    __syncthreads();

    for (int i = tid; i < 64*65; i += 256) Vm[i] = 0.f;
    __syncthreads();
    if (tid < 64) Vm[tid*65 + tid] = 1.f;
    __syncthreads();

    {
        int p = tid >> 3, lane = tid & 7;
        for (int sw = 0; sw < NSWEEP; sw++) {
            for (int r = 0; r < 63; r++) {
                int ci, cj;
                if (p == 0) { ci = 63; cj = r; }
                else { ci = (r + p) % 63; cj = (r - p + 63) % 63; }
                float aa = 0.f, bb = 0.f, gg = 0.f;
                for (int q = lane; q < 64; q += 8) {
                    float gi = G[q*65 + ci], gj = G[q*65 + cj];
                    aa = fmaf(gi, gi, aa);
                    bb = fmaf(gj, gj, bb);
                    gg = fmaf(gi, gj, gg);
                }
#pragma unroll
                for (int o = 4; o > 0; o >>= 1) {
                    aa += __shfl_xor_sync(0xffffffffu, aa, o);
                    bb += __shfl_xor_sync(0xffffffffu, bb, o);
                    gg += __shfl_xor_sync(0xffffffffu, gg, o);
                }
                float c_ = 1.f, s_ = 0.f;
                if (fabsf(gg) > 1e-30f) {
                    float zeta = (bb - aa) / (2.0f * gg);
                    float t = copysignf(1.0f, zeta) / (fabsf(zeta) + sqrtf(1.0f + zeta*zeta));
                    c_ = 1.0f / sqrtf(1.0f + t*t);
                    s_ = c_ * t;
                }
                if (s_ != 0.f) {
                    for (int q = lane; q < 64; q += 8) {
                        float gi = G[q*65 + ci], gj = G[q*65 + cj];
                        G[q*65 + ci] = c_*gi - s_*gj;
                        G[q*65 + cj] = s_*gi + c_*gj;
                        float vi = Vm[q*65 + ci], vj = Vm[q*65 + cj];
                        Vm[q*65 + ci] = c_*vi - s_*vj;
                        Vm[q*65 + cj] = s_*vi + c_*vj;
                    }
                }
                __syncthreads();
            }
        }
    }

    if (tid < 64) {
        float ss = 0.f;
        for (int q = 0; q < 64; q++) { float g = G[q*65 + tid]; ss = fmaf(g, g, ss); }
        svec[tid] = sqrtf(ss);
    }
    __syncthreads();
    if (tid < 64) {
        float smax = 0.f;
        for (int c = 0; c < 64; c++) smax = fmaxf(smax, svec[c]);
        float cut = 7.62939453125e-5f * smax;
        float s = svec[tid];
        wvec[tid] = (s > cut) ? 1.0f / (s * s) : 0.0f;
    }
    __syncthreads();

    for (int i = tid; i < 4096; i += 256)
        W[(i >> 6)*65 + (i & 63)] = BV[(size_t)bh*4096 + i];
    __syncthreads();
    float t1[4][4] = {};
    for (int q = 0; q < 64; q++) {
        float a[4], bb[4];
#pragma unroll
        for (int x = 0; x < 4; x++) a[x]  = G[q*65 + ti*4+x];
#pragma unroll
        for (int y = 0; y < 4; y++) bb[y] = W[q*65 + tj*4+y];
#pragma unroll
        for (int x = 0; x < 4; x++)
#pragma unroll
            for (int y = 0; y < 4; y++)
                t1[x][y] = fmaf(a[x], bb[y], t1[x][y]);
    }
#pragma unroll
    for (int x = 0; x < 4; x++) {
        float w = wvec[ti*4+x];
#pragma unroll
        for (int y = 0; y < 4; y++) t1[x][y] *= w;
    }
    __syncthreads();
#pragma unroll
    for (int x = 0; x < 4; x++)
#pragma unroll
        for (int y = 0; y < 4; y++)
            G[(ti*4+x)*65 + tj*4+y] = t1[x][y];
    __syncthreads();

    float cb[4][4] = {};
    for (int q = 0; q < 64; q++) {
        float a[4], bb[4];
#pragma unroll
        for (int x = 0; x < 4; x++) a[x]  = Vm[(ti*4+x)*65 + q];
#pragma unroll
        for (int y = 0; y < 4; y++) bb[y] = G[q*65 + tj*4+y];
#pragma unroll
        for (int x = 0; x < 4; x++)
#pragma unroll
            for (int y = 0; y < 4; y++)
                cb[x][y] = fmaf(a[x], bb[y], cb[x][y]);
    }
#pragma unroll
    for (int x = 0; x < 4; x++)
#pragma unroll
        for (int y = 0; y < 4; y++)
            CBV[(size_t)bh*4096 + (ti*4+x)*64 + tj*4+y] = cb[x][y];
}

// ---------------------------------------------------------------------------
// Y = A_hat @ CBV per head -> fp16 hi (merged-head layout).
// ---------------------------------------------------------------------------
__global__ __launch_bounds__(256) void av_kernel(
    const float* __restrict__ Ahat, const float* __restrict__ CBV,
    __half* __restrict__ ahp)
{
    int bh = blockIdx.y;
    int b = bh >> 4, hh = bh & 15;
    int t0 = blockIdx.x * 64;
    __shared__ float As[64*65];
    __shared__ float Cs[64*65];
    int tid = threadIdx.x;
    for (int i = tid; i < 4096; i += 256) {
        int tl = i >> 6, c = i & 63;
        As[c*65 + tl] = Ahat[((size_t)bh*T_SEQ + t0 + tl)*64 + c];
        Cs[tl*65 + c] = CBV[(size_t)bh*4096 + i];
    }
    __syncthreads();
    int ti = tid >> 4, tj = tid & 15;
    float acc[4][4] = {};
    for (int c = 0; c < 64; c++) {
        float a[4], bb[4];
#pragma unroll
        for (int x = 0; x < 4; x++) a[x]  = As[c*65 + ti*4+x];
#pragma unroll
        for (int y = 0; y < 4; y++) bb[y] = Cs[c*65 + tj*4+y];
#pragma unroll
        for (int x = 0; x < 4; x++)
#pragma unroll
            for (int y = 0; y < 4; y++)
                acc[x][y] = fmaf(a[x], bb[y], acc[x][y]);
    }
#pragma unroll
    for (int x = 0; x < 4; x++) {
        size_t idx = ((size_t)b*T_SEQ + t0 + ti*4 + x)*DMODEL + hh*64 + tj*4;
#pragma unroll
        for (int y = 0; y < 4; y += 2) {
            __half2 Hp;
            Hp.x = __float2half(acc[x][y]);
            Hp.y = __float2half(acc[x][y+1]);
            *(__half2*)(ahp + idx + y) = Hp;
        }
    }
}

// ---------------------------------------------------------------------------
extern "C" void kernel_launch(void* const* d_in, const int* in_sizes, int n_in,
                              void* d_out, int out_size)
{
    (void)in_sizes; (void)n_in; (void)out_size;
    const float* x = (const float*)d_in[0];
    const float* Wq = (const float*)d_in[1];
    const float* Wk = (const float*)d_in[2];
    const float* Wv = (const float*)d_in[3];
    const float* Wo = (const float*)d_in[4];
    float* out = (float*)d_out;

    float *QKV, *A, *S, *Qlm, *Klm, *BV, *CBV, *BVp, *csump;
    __half *xh, *wh, *wl, *ah;
    cudaGetSymbolAddress((void**)&QKV,   g_QKV);
    cudaGetSymbolAddress((void**)&A,     g_A);
    cudaGetSymbolAddress((void**)&S,     g_S);
    cudaGetSymbolAddress((void**)&Qlm,   g_Qlm);
    cudaGetSymbolAddress((void**)&Klm,   g_Klm);
    cudaGetSymbolAddress((void**)&BV,    g_BV);
    cudaGetSymbolAddress((void**)&CBV,   g_CBV);
    cudaGetSymbolAddress((void**)&BVp,   g_BVpart);
    cudaGetSymbolAddress((void**)&csump, g_csump);
    cudaGetSymbolAddress((void**)&xh,    g_xh);
    cudaGetSymbolAddress((void**)&wh,    g_wh);
    cudaGetSymbolAddress((void**)&wl,    g_wl);
    cudaGetSymbolAddress((void**)&ah,    g_ah);

    float* Q = QKV;
    float* K = QKV + (size_t)NROWS * DMODEL;
    float* V = QKV + 2 * (size_t)NROWS * DMODEL;

    cudaFuncSetAttribute(pinv_cbv_kernel,
                         cudaFuncAttributeMaxDynamicSharedMemorySize, 50432);
    cudaFuncSetAttribute(gemm_mma_kernel,
                         cudaFuncAttributeMaxDynamicSharedMemorySize, GM_SMEM);

    // splits (W hi+lo; x hi only)
    wsplit2_kernel<<<dim3(1024, 2), 256>>>((const float4*)Wq, (const float4*)Wk,
        (__half2*)wh, (__half2*)wl);
    wsplit2_kernel<<<dim3(1024, 2), 256>>>((const float4*)Wv, (const float4*)Wo,
        (__half2*)(wh + 2*(size_t)DMODEL*DMODEL), (__half2*)(wl + 2*(size_t)DMODEL*DMODEL));
    const int half4 = NROWS*DMODEL/8;
    xsplit_kernel<<<4096, 256>>>((const float4*)x, (__half2*)xh, half4);
    xsplit_kernel<<<4096, 256>>>((const float4*)x + half4,
        (__half2*)(xh + (size_t)NROWS*DMODEL/2), half4);

    // fused Q/K/V projection
    dim3 gq(DMODEL/128, NROWS/128, 3);
    gemm_mma_kernel<<<gq, 256, GM_SMEM>>>(xh, wh, wl, QKV,
                                          NROWS, DMODEL, DMODEL,
                                          (size_t)DMODEL*DMODEL, (size_t)NROWS*DMODEL);

    landmark_kernel<<<dim3(64, NBH, 2), 64>>>(Q, K, Qlm, Klm);
    scores_kernel<<<dim3(T_SEQ/128, NBH), 128>>>(Q, Klm, A, 1);
    scores_kernel<<<dim3(T_SEQ/128, NBH), 128>>>(K, Qlm, S, 0);
    bv_partial_kernel<<<dim3(8, NBH), 256>>>(S, V, BVp, csump);
    bv_reduce_kernel<<<NBH, 256>>>(BVp, csump, BV);
    pinv_cbv_kernel<<<NBH, 256, 50432>>>(Qlm, Klm, BV, CBV);
    av_kernel<<<dim3(T_SEQ/64, NBH), 256>>>(A, CBV, ah);

    dim3 go(DMODEL/128, NROWS/128, 1);
    gemm_mma_kernel<<<go, 256, GM_SMEM>>>(ah,
                                          wh + 3*(size_t)DMODEL*DMODEL,
                                          wl + 3*(size_t)DMODEL*DMODEL, out,
                                          NROWS, DMODEL, DMODEL, 0, 0);
}

// round 9
// speedup vs baseline: 1.2460x; 1.0133x over previous
#include <cuda_runtime.h>
#include <cuda_fp16.h>
#include <math.h>
#include <stdint.h>

// Problem constants: B=2, T=4096, d_model=1024, H=16, d_head=64, m=64
#define T_SEQ 4096
#define DMODEL 1024
#define NBH    32      // B*H
#define NROWS  8192    // B*T
#define NSWEEP 12

// ---------------- device scratch (no runtime allocation allowed) ----------------
__device__ __align__(16) float g_QKV[3 * NROWS * DMODEL];   // Q | K | V
__device__ __align__(16) float g_A[NBH * T_SEQ * 64];       // A_hat  [bh][t][mi]
__device__ __align__(16) float g_S[NBH * T_SEQ * 64];       // exp(B scores)
__device__ __align__(16) float g_Qlm[NBH * 64 * 64];
__device__ __align__(16) float g_Klm[NBH * 64 * 64];
__device__ __align__(16) float g_BV[NBH * 64 * 64];
__device__ __align__(16) float g_CBV[NBH * 64 * 64];
__device__ __align__(16) float g_BVpart[NBH * 8 * 64 * 64];
__device__ float g_csump[NBH * 8 * 64];
// fp16 splits: x hi only; weights hi+lo; attn hi+lo
__device__ __align__(16) __half g_xh[NROWS * DMODEL];
__device__ __align__(16) __half g_wh[4][DMODEL * DMODEL];
__device__ __align__(16) __half g_wl[4][DMODEL * DMODEL];
__device__ __align__(16) __half g_ah[NROWS * DMODEL];
__device__ __align__(16) __half g_al[NROWS * DMODEL];

// =====================  helpers  =====================
__device__ __forceinline__ uint32_t smem_u32(const void* p) {
    return (uint32_t)__cvta_generic_to_shared(p);
}
__device__ __forceinline__ void cp16(uint32_t dst, const void* src) {
    asm volatile("cp.async.cg.shared.global [%0], [%1], 16;" :: "r"(dst), "l"(src));
}
__device__ __forceinline__ void ldsm_x4(uint32_t* r, uint32_t addr) {
    asm volatile("ldmatrix.sync.aligned.m8n8.x4.shared.b16 {%0,%1,%2,%3}, [%4];"
        : "=r"(r[0]), "=r"(r[1]), "=r"(r[2]), "=r"(r[3]) : "r"(addr));
}
#define MMA16816F(d, a, b) \
    asm volatile("mma.sync.aligned.m16n8k16.row.col.f32.f16.f16.f32 " \
        "{%0,%1,%2,%3},{%4,%5,%6,%7},{%8,%9},{%0,%1,%2,%3};" \
        : "+f"((d)[0]), "+f"((d)[1]), "+f"((d)[2]), "+f"((d)[3]) \
        : "r"((a)[0]), "r"((a)[1]), "r"((a)[2]), "r"((a)[3]), \
          "r"((b)[0]), "r"((b)[1]))

// ---------------------------------------------------------------------------
// splits
// ---------------------------------------------------------------------------
__global__ void xsplit_kernel(const float4* __restrict__ in,
                              __half2* __restrict__ hi, int n4)
{
    int i = blockIdx.x * 256 + threadIdx.x;
    if (i >= n4) return;
    float4 v = in[i];
    __half2 H0, H1;
    H0.x = __float2half(v.x); H0.y = __float2half(v.y);
    H1.x = __float2half(v.z); H1.y = __float2half(v.w);
    hi[2*i] = H0; hi[2*i+1] = H1;
}

// all four weight matrices in one launch; blockIdx.y selects. hi + lo.
__global__ void wsplit4_kernel(const float4* __restrict__ W0, const float4* __restrict__ W1,
                               const float4* __restrict__ W2, const float4* __restrict__ W3,
                               __half2* __restrict__ hi, __half2* __restrict__ lo)
{
    int w = blockIdx.y;
    const float4* src = (w == 0) ? W0 : (w == 1) ? W1 : (w == 2) ? W2 : W3;
    int i = blockIdx.x * 256 + threadIdx.x;
    int o2 = w * (DMODEL*DMODEL/2) + 2*i;
    float4 v = src[i];
    __half h0 = __float2half(v.x), h1 = __float2half(v.y);
    __half h2 = __float2half(v.z), h3 = __float2half(v.w);
    __half2 H0, H1, L0, L1;
    H0.x = h0; H0.y = h1; H1.x = h2; H1.y = h3;
    L0.x = __float2half(v.x - __half2float(h0));
    L0.y = __float2half(v.y - __half2float(h1));
    L1.x = __float2half(v.z - __half2float(h2));
    L1.y = __float2half(v.w - __half2float(h3));
    hi[o2] = H0; hi[o2+1] = H1;
    lo[o2] = L0; lo[o2+1] = L1;
}

// ---------------------------------------------------------------------------
// 2-term NT GEMM: C = Ah*Bh^T + Ah*Bl^T (fp32 acc). 128x128 tile, 8 warps,
// 3-stage cp.async. __launch_bounds__(256,2) -> 2 CTAs/SM.
// ---------------------------------------------------------------------------
#define GM_ROWB  80
#define GM_TILE  (128 * GM_ROWB)      // 10240
#define G2_STAGE (3 * GM_TILE)        // 30720  (AH, BH, BL)
#define G2_SMEM  (3 * G2_STAGE)       // 92160

__global__ __launch_bounds__(256, 2) void gemm_mma2_kernel(
    const __half* __restrict__ Ahi,
    const __half* __restrict__ Bhi_base, const __half* __restrict__ Blo_base,
    float* __restrict__ C_base, int M, int N, int K,
    size_t wstride, size_t cstride)
{
    extern __shared__ __align__(128) char smem[];
    const uint32_t sb = smem_u32(smem);
    const int tid = threadIdx.x;
    const int z = blockIdx.z;
    const __half* Bhi = Bhi_base + (size_t)z * wstride;
    const __half* Blo = Blo_base + (size_t)z * wstride;
    float* C = C_base + (size_t)z * cstride;

    const int m0 = blockIdx.y * 128, n0 = blockIdx.x * 128;
    const int wid = tid >> 5, lane = tid & 31;
    const int wr = (wid & 3) * 32;
    const int wc = (wid >> 2) * 64;
    const int lrow = tid >> 2;
    const int lseg = tid & 3;

    const int nchunks = K >> 5;

    auto load_stage = [&](int s, int kc) {
        uint32_t st = sb + s * G2_STAGE;
#pragma unroll
        for (int i = 0; i < 2; i++) {
            int row = lrow + i * 64;
            uint32_t off = row * GM_ROWB + lseg * 16;
            cp16(st +             off, Ahi + (size_t)(m0 + row) * K + kc + lseg * 8);
            cp16(st + GM_TILE   + off, Bhi + (size_t)(n0 + row) * K + kc + lseg * 8);
            cp16(st + 2*GM_TILE + off, Blo + (size_t)(n0 + row) * K + kc + lseg * 8);
        }
        asm volatile("cp.async.commit_group;" ::: "memory");
    };

    load_stage(0, 0);
    load_stage(1, 32);
    load_stage(2, 64);

    float accF[2][8][4];
#pragma unroll
    for (int mt = 0; mt < 2; mt++)
#pragma unroll
        for (int nt = 0; nt < 8; nt++)
#pragma unroll
            for (int q = 0; q < 4; q++) accF[mt][nt][q] = 0.f;

    const uint32_t aBase = (uint32_t)(wr + (lane & 15)) * GM_ROWB + (uint32_t)(lane >> 4) * 16;
    const uint32_t bBase = (uint32_t)(wc + (lane & 7) + ((lane >> 4) * 8)) * GM_ROWB
                         + (uint32_t)((lane >> 3) & 1) * 16;

    const int fr = lane >> 2;
    const int fc = (lane & 3) * 2;

    for (int c = 0; c < nchunks; c++) {
        int s = c % 3;
        asm volatile("cp.async.wait_group 2;" ::: "memory");
        __syncthreads();
        uint32_t st  = sb + s * G2_STAGE;
        uint32_t tAH = st;
        uint32_t tBH = st + GM_TILE;
        uint32_t tBL = st + 2*GM_TILE;

#pragma unroll
        for (int k16 = 0; k16 < 2; k16++) {
            uint32_t kb = k16 * 32;
            uint32_t aH[2][4];
#pragma unroll
            for (int mt = 0; mt < 2; mt++)
                ldsm_x4(aH[mt], tAH + aBase + mt * 16 * GM_ROWB + kb);
            uint32_t bH[8][2], bL[8][2];
#pragma unroll
            for (int p = 0; p < 4; p++) {
                uint32_t bo = bBase + p * 16 * GM_ROWB + kb;
                uint32_t tH[4], tL[4];
                ldsm_x4(tH, tBH + bo);
                ldsm_x4(tL, tBL + bo);
                bH[2*p][0] = tH[0]; bH[2*p][1] = tH[1];
                bH[2*p+1][0] = tH[2]; bH[2*p+1][1] = tH[3];
                bL[2*p][0] = tL[0]; bL[2*p][1] = tL[1];
                bL[2*p+1][0] = tL[2]; bL[2*p+1][1] = tL[3];
            }
#pragma unroll
            for (int mt = 0; mt < 2; mt++)
#pragma unroll
                for (int nt = 0; nt < 8; nt++)
                    MMA16816F(accF[mt][nt], aH[mt], bH[nt]);
#pragma unroll
            for (int mt = 0; mt < 2; mt++)
#pragma unroll
                for (int nt = 0; nt < 8; nt++)
                    MMA16816F(accF[mt][nt], aH[mt], bL[nt]);
        }
        __syncthreads();
        if (c + 3 < nchunks) {
            load_stage(s, (c + 3) * 32);
        } else {
            asm volatile("cp.async.commit_group;" ::: "memory");
        }
    }

#pragma unroll
    for (int mt = 0; mt < 2; mt++) {
#pragma unroll
        for (int nt = 0; nt < 8; nt++) {
            int row = m0 + wr + mt*16 + fr;
            int col = n0 + wc + nt*8 + fc;
            *(float2*)(C + (size_t)row * N + col) =
                make_float2(accF[mt][nt][0], accF[mt][nt][1]);
            *(float2*)(C + (size_t)(row + 8) * N + col) =
                make_float2(accF[mt][nt][2], accF[mt][nt][3]);
        }
    }
}

// ---------------------------------------------------------------------------
// 3-term NT GEMM (out-projection): C = Ah*Bh + Ah*Bl + Al*Bh (fp32 acc).
// 128x128 tile, 8 warps, 2-stage cp.async (4 tiles/stage), 2 CTAs/SM.
// ---------------------------------------------------------------------------
#define G3_STAGE (4 * GM_TILE)        // 40960 (AH, AL, BH, BL)
#define G3_SMEM  (2 * G3_STAGE)       // 81920

__global__ __launch_bounds__(256, 2) void gemm_mma3_kernel(
    const __half* __restrict__ Ahi, const __half* __restrict__ Alo,
    const __half* __restrict__ Bhi, const __half* __restrict__ Blo,
    float* __restrict__ C, int M, int N, int K)
{
    extern __shared__ __align__(128) char smem[];
    const uint32_t sb = smem_u32(smem);
    const int tid = threadIdx.x;
    const int m0 = blockIdx.y * 128, n0 = blockIdx.x * 128;
    const int wid = tid >> 5, lane = tid & 31;
    const int wr = (wid & 3) * 32;
    const int wc = (wid >> 2) * 64;
    const int lrow = tid >> 2;
    const int lseg = tid & 3;

    const int nchunks = K >> 5;

    auto load_stage = [&](int s, int kc) {
        uint32_t st = sb + s * G3_STAGE;
#pragma unroll
        for (int i = 0; i < 2; i++) {
            int row = lrow + i * 64;
            uint32_t off = row * GM_ROWB + lseg * 16;
            cp16(st +             off, Ahi + (size_t)(m0 + row) * K + kc + lseg * 8);
            cp16(st + GM_TILE   + off, Alo + (size_t)(m0 + row) * K + kc + lseg * 8);
            cp16(st + 2*GM_TILE + off, Bhi + (size_t)(n0 + row) * K + kc + lseg * 8);
            cp16(st + 3*GM_TILE + off, Blo + (size_t)(n0 + row) * K + kc + lseg * 8);
        }
        asm volatile("cp.async.commit_group;" ::: "memory");
    };

    load_stage(0, 0);
    load_stage(1, 32);

    float accF[2][8][4];
#pragma unroll
    for (int mt = 0; mt < 2; mt++)
#pragma unroll
        for (int nt = 0; nt < 8; nt++)
#pragma unroll
            for (int q = 0; q < 4; q++) accF[mt][nt][q] = 0.f;

    const uint32_t aBase = (uint32_t)(wr + (lane & 15)) * GM_ROWB + (uint32_t)(lane >> 4) * 16;
    const uint32_t bBase = (uint32_t)(wc + (lane & 7) + ((lane >> 4) * 8)) * GM_ROWB
                         + (uint32_t)((lane >> 3) & 1) * 16;

    const int fr = lane >> 2;
    const int fc = (lane & 3) * 2;

    for (int c = 0; c < nchunks; c++) {
        int s = c & 1;
        asm volatile("cp.async.wait_group 1;" ::: "memory");
        __syncthreads();
        uint32_t st  = sb + s * G3_STAGE;
        uint32_t tAH = st;
        uint32_t tAL = st + GM_TILE;
        uint32_t tBH = st + 2*GM_TILE;
        uint32_t tBL = st + 3*GM_TILE;

#pragma unroll
        for (int k16 = 0; k16 < 2; k16++) {
            uint32_t kb = k16 * 32;
            uint32_t aH[2][4], aL[2][4];
#pragma unroll
            for (int mt = 0; mt < 2; mt++) {
                uint32_t ao = aBase + mt * 16 * GM_ROWB + kb;
                ldsm_x4(aH[mt], tAH + ao);
                ldsm_x4(aL[mt], tAL + ao);
            }
            uint32_t bH[8][2], bL[8][2];
#pragma unroll
            for (int p = 0; p < 4; p++) {
                uint32_t bo = bBase + p * 16 * GM_ROWB + kb;
                uint32_t tH[4], tL[4];
                ldsm_x4(tH, tBH + bo);
                ldsm_x4(tL, tBL + bo);
                bH[2*p][0] = tH[0]; bH[2*p][1] = tH[1];
                bH[2*p+1][0] = tH[2]; bH[2*p+1][1] = tH[3];
                bL[2*p][0] = tL[0]; bL[2*p][1] = tL[1];
                bL[2*p+1][0] = tL[2]; bL[2*p+1][1] = tL[3];
            }
#pragma unroll
            for (int mt = 0; mt < 2; mt++)
#pragma unroll
                for (int nt = 0; nt < 8; nt++)
                    MMA16816F(accF[mt][nt], aH[mt], bH[nt]);
#pragma unroll
            for (int mt = 0; mt < 2; mt++)
#pragma unroll
                for (int nt = 0; nt < 8; nt++)
                    MMA16816F(accF[mt][nt], aH[mt], bL[nt]);
#pragma unroll
            for (int mt = 0; mt < 2; mt++)
#pragma unroll
                for (int nt = 0; nt < 8; nt++)
                    MMA16816F(accF[mt][nt], aL[mt], bH[nt]);
        }
        __syncthreads();
        if (c + 2 < nchunks) {
            load_stage(s, (c + 2) * 32);
        } else {
            asm volatile("cp.async.commit_group;" ::: "memory");
        }
    }

#pragma unroll
    for (int mt = 0; mt < 2; mt++) {
#pragma unroll
        for (int nt = 0; nt < 8; nt++) {
            int row = m0 + wr + mt*16 + fr;
            int col = n0 + wc + nt*8 + fc;
            *(float2*)(C + (size_t)row * N + col) =
                make_float2(accF[mt][nt][0], accF[mt][nt][1]);
            *(float2*)(C + (size_t)(row + 8) * N + col) =
                make_float2(accF[mt][nt][2], accF[mt][nt][3]);
        }
    }
}

// ---------------------------------------------------------------------------
// Landmarks: segment mean over 64 consecutive t.
// ---------------------------------------------------------------------------
__global__ void landmark_kernel(const float* __restrict__ Q, const float* __restrict__ K,
                                float* __restrict__ Qlm, float* __restrict__ Klm)
{
    int mi = blockIdx.x, bh = blockIdx.y;
    int b = bh >> 4, h = bh & 15;
    const float* src = blockIdx.z ? K : Q;
    float* dst = blockIdx.z ? Klm : Qlm;
    int d = threadIdx.x;
    const float* p = src + ((size_t)b * T_SEQ + mi * 64) * DMODEL + h * 64 + d;
    float s = 0.f;
#pragma unroll 8
    for (int r = 0; r < 64; r++) s += p[(size_t)r * DMODEL];
    dst[((size_t)bh * 64 + mi) * 64 + d] = s * 0.015625f;
}

// ---------------------------------------------------------------------------
// scores: s = (X_row(t) . Ylm[mi]) / 8.  mode 1: row softmax; mode 0: exp(s).
// ---------------------------------------------------------------------------
__global__ __launch_bounds__(128) void scores_kernel(
    const float* __restrict__ X, const float* __restrict__ Ylm,
    float* __restrict__ out, int do_softmax)
{
    int bh = blockIdx.y;
    int b = bh >> 4, h = bh & 15;
    int tid = threadIdx.x;
    int t = blockIdx.x * 128 + tid;
    __shared__ float4 Ks[1024];
    __shared__ float Ssc[64 * 128];
    const float4* Ysrc = (const float4*)(Ylm + (size_t)bh * 4096);
    for (int i = tid; i < 1024; i += 128) Ks[i] = Ysrc[i];
    __syncthreads();

    const float4* xrow = (const float4*)(X + ((size_t)b * T_SEQ + t) * DMODEL + h * 64);
    float q[64];
#pragma unroll
    for (int d4 = 0; d4 < 16; d4++) {
        float4 v = xrow[d4];
        q[4*d4+0]=v.x; q[4*d4+1]=v.y; q[4*d4+2]=v.z; q[4*d4+3]=v.w;
    }
    for (int mi = 0; mi < 64; mi++) {
        float acc = 0.f;
#pragma unroll
        for (int d4 = 0; d4 < 16; d4++) {
            float4 k4 = Ks[mi*16 + d4];
            acc = fmaf(q[4*d4+0], k4.x, acc);
            acc = fmaf(q[4*d4+1], k4.y, acc);
            acc = fmaf(q[4*d4+2], k4.z, acc);
            acc = fmaf(q[4*d4+3], k4.w, acc);
        }
        Ssc[mi*128 + tid] = acc * 0.125f;
    }
    float* orow = out + ((size_t)bh * T_SEQ + t) * 64;
    if (do_softmax) {
        float m = -INFINITY;
        for (int mi = 0; mi < 64; mi++) m = fmaxf(m, Ssc[mi*128 + tid]);
        float z = 0.f;
        for (int mi = 0; mi < 64; mi++) {
            float e = expf(Ssc[mi*128 + tid] - m);
            Ssc[mi*128 + tid] = e; z += e;
        }
        float inv = 1.0f / z;
        for (int mi = 0; mi < 64; mi += 4) {
            float4 o = make_float4(Ssc[(mi+0)*128+tid]*inv, Ssc[(mi+1)*128+tid]*inv,
                                   Ssc[(mi+2)*128+tid]*inv, Ssc[(mi+3)*128+tid]*inv);
            *(float4*)(orow + mi) = o;
        }
    } else {
        for (int mi = 0; mi < 64; mi += 4) {
            float4 o = make_float4(expf(Ssc[(mi+0)*128+tid]), expf(Ssc[(mi+1)*128+tid]),
                                   expf(Ssc[(mi+2)*128+tid]), expf(Ssc[(mi+3)*128+tid]));
            *(float4*)(orow + mi) = o;
        }
    }
}

// ---------------------------------------------------------------------------
// BV partials over 512-row chunks: part = E^T V + per-column sums of E.
// ---------------------------------------------------------------------------
__global__ __launch_bounds__(256) void bv_partial_kernel(
    const float* __restrict__ Se, const float* __restrict__ V,
    float* __restrict__ part, float* __restrict__ csump)
{
    int chunk = blockIdx.x, bh = blockIdx.y;
    int b = bh >> 4, h = bh & 15;
    __shared__ float Es[64][65];
    __shared__ float Vs[64][65];
    __shared__ float sred[256];
    int tid = threadIdx.x;
    int ti = tid >> 4, tj = tid & 15;
    float acc[4][4] = {};
    float cs = 0.f;
    for (int t0 = chunk*512; t0 < chunk*512 + 512; t0 += 64) {
        __syncthreads();
        for (int i = tid; i < 4096; i += 256) {
            int r = i >> 6, c = i & 63;
            float e = Se[((size_t)bh*T_SEQ + t0 + r)*64 + c];
            Es[r][c] = e;
            cs += e;
            Vs[r][c] = V[((size_t)b*T_SEQ + t0 + r)*DMODEL + h*64 + c];
        }
        __syncthreads();
#pragma unroll 4
        for (int r = 0; r < 64; r++) {
            float a[4], bb[4];
#pragma unroll
            for (int x = 0; x < 4; x++) a[x]  = Es[r][ti*4+x];
#pragma unroll
            for (int y = 0; y < 4; y++) bb[y] = Vs[r][tj*4+y];
#pragma unroll
            for (int x = 0; x < 4; x++)
#pragma unroll
                for (int y = 0; y < 4; y++)
                    acc[x][y] = fmaf(a[x], bb[y], acc[x][y]);
        }
    }
    float* dst = part + ((size_t)(bh*8 + chunk)) * 4096;
#pragma unroll
    for (int x = 0; x < 4; x++)
#pragma unroll
        for (int y = 0; y < 4; y++)
            dst[(ti*4+x)*64 + tj*4+y] = acc[x][y];
    sred[tid] = cs;
    __syncthreads();
    if (tid < 64)
        csump[(size_t)(bh*8 + chunk)*64 + tid] =
            sred[tid] + sred[tid+64] + sred[tid+128] + sred[tid+192];
}

__global__ void bv_reduce_kernel(const float* __restrict__ part,
                                 const float* __restrict__ csump, float* __restrict__ BV)
{
    int bh = blockIdx.x, tid = threadIdx.x;
    __shared__ float den[64];
    if (tid < 64) {
        float s = 0.f;
#pragma unroll
        for (int ch = 0; ch < 8; ch++) s += csump[(size_t)(bh*8 + ch)*64 + tid];
        den[tid] = 1.0f / s;
    }
    __syncthreads();
    for (int i = tid; i < 4096; i += 256) {
        float s = 0.f;
#pragma unroll
        for (int ch = 0; ch < 8; ch++) s += part[((size_t)(bh*8 + ch))*4096 + i];
        BV[(size_t)bh*4096 + i] = s * den[i >> 6];
    }
}

// ---------------------------------------------------------------------------
// pinv(C_hat) @ BV via one-sided Jacobi SVD, JAX cutoff rcond=10*64*eps.
// ---------------------------------------------------------------------------
__global__ __launch_bounds__(256) void pinv_cbv_kernel(
    const float* __restrict__ Qlm, const float* __restrict__ Klm,
    const float* __restrict__ BV, float* __restrict__ CBV)
{
    extern __shared__ float sp[];
    float* G    = sp;
    float* Vm   = sp + 4160;
    float* W    = sp + 8320;
    float* svec = sp + 12480;
    float* wvec = sp + 12544;
    int bh = blockIdx.x;
    int tid = threadIdx.x;
    int ti = tid >> 4, tj = tid & 15;

    for (int i = tid; i < 4096; i += 256) {
        int r = i >> 6, c = i & 63;
        Vm[r*65 + c] = Qlm[(size_t)bh*4096 + i];
        W [r*65 + c] = Klm[(size_t)bh*4096 + i];
    }
    __syncthreads();

    {
        float cacc[4][4] = {};
        for (int d = 0; d < 64; d++) {
            float qa[4], kb[4];
#pragma unroll
            for (int x = 0; x < 4; x++) qa[x] = Vm[(ti*4+x)*65 + d];
#pragma unroll
            for (int y = 0; y < 4; y++) kb[y] = W[(tj*4+y)*65 + d];
#pragma unroll
            for (int x = 0; x < 4; x++)
#pragma unroll
                for (int y = 0; y < 4; y++)
                    cacc[x][y] = fmaf(qa[x], kb[y], cacc[x][y]);
        }
        __syncthreads();
#pragma unroll
        for (int x = 0; x < 4; x++)
#pragma unroll
            for (int y = 0; y < 4; y++)
                G[(ti*4+x)*65 + tj*4+y] = cacc[x][y] * 0.125f;
    }
    __syncthreads();

    if (tid < 64) {
        float mx = -INFINITY;
        for (int c = 0; c < 64; c++) mx = fmaxf(mx, G[tid*65 + c]);
        float z = 0.f;
        for (int c = 0; c < 64; c++) {
            float e = expf(G[tid*65 + c] - mx);
            G[tid*65 + c] = e; z += e;
        }
        float inv = 1.f / z;
        for (int c = 0; c < 64; c++) G[tid*65 + c] *= inv;
    }
    __syncthreads();

    for (int i = tid; i < 64*65; i += 256) Vm[i] = 0.f;
    __syncthreads();
    if (tid < 64) Vm[tid*65 + tid] = 1.f;
    __syncthreads();

    {
        int p = tid >> 3, lane = tid & 7;
        for (int sw = 0; sw < NSWEEP; sw++) {
            for (int r = 0; r < 63; r++) {
                int ci, cj;
                if (p == 0) { ci = 63; cj = r; }
                else { ci = (r + p) % 63; cj = (r - p + 63) % 63; }
                float aa = 0.f, bb = 0.f, gg = 0.f;
                for (int q = lane; q < 64; q += 8) {
                    float gi = G[q*65 + ci], gj = G[q*65 + cj];
                    aa = fmaf(gi, gi, aa);
                    bb = fmaf(gj, gj, bb);
                    gg = fmaf(gi, gj, gg);
                }
#pragma unroll
                for (int o = 4; o > 0; o >>= 1) {
                    aa += __shfl_xor_sync(0xffffffffu, aa, o);
                    bb += __shfl_xor_sync(0xffffffffu, bb, o);
                    gg += __shfl_xor_sync(0xffffffffu, gg, o);
                }
                float c_ = 1.f, s_ = 0.f;
                if (fabsf(gg) > 1e-30f) {
                    float zeta = (bb - aa) / (2.0f * gg);
                    float t = copysignf(1.0f, zeta) / (fabsf(zeta) + sqrtf(1.0f + zeta*zeta));
                    c_ = 1.0f / sqrtf(1.0f + t*t);
                    s_ = c_ * t;
                }
                if (s_ != 0.f) {
                    for (int q = lane; q < 64; q += 8) {
                        float gi = G[q*65 + ci], gj = G[q*65 + cj];
                        G[q*65 + ci] = c_*gi - s_*gj;
                        G[q*65 + cj] = s_*gi + c_*gj;
                        float vi = Vm[q*65 + ci], vj = Vm[q*65 + cj];
                        Vm[q*65 + ci] = c_*vi - s_*vj;
                        Vm[q*65 + cj] = s_*vi + c_*vj;
                    }
                }
                __syncthreads();
            }
        }
    }

    if (tid < 64) {
        float ss = 0.f;
        for (int q = 0; q < 64; q++) { float g = G[q*65 + tid]; ss = fmaf(g, g, ss); }
        svec[tid] = sqrtf(ss);
    }
    __syncthreads();
    if (tid < 64) {
        float smax = 0.f;
        for (int c = 0; c < 64; c++) smax = fmaxf(smax, svec[c]);
        float cut = 7.62939453125e-5f * smax;
        float s = svec[tid];
        wvec[tid] = (s > cut) ? 1.0f / (s * s) : 0.0f;
    }
    __syncthreads();

    for (int i = tid; i < 4096; i += 256)
        W[(i >> 6)*65 + (i & 63)] = BV[(size_t)bh*4096 + i];
    __syncthreads();
    float t1[4][4] = {};
    for (int q = 0; q < 64; q++) {
        float a[4], bb[4];
#pragma unroll
        for (int x = 0; x < 4; x++) a[x]  = G[q*65 + ti*4+x];
#pragma unroll
        for (int y = 0; y < 4; y++) bb[y] = W[q*65 + tj*4+y];
#pragma unroll
        for (int x = 0; x < 4; x++)
#pragma unroll
            for (int y = 0; y < 4; y++)
                t1[x][y] = fmaf(a[x], bb[y], t1[x][y]);
    }
#pragma unroll
    for (int x = 0; x < 4; x++) {
        float w = wvec[ti*4+x];
#pragma unroll
        for (int y = 0; y < 4; y++) t1[x][y] *= w;
    }
    __syncthreads();
#pragma unroll
    for (int x = 0; x < 4; x++)
#pragma unroll
        for (int y = 0; y < 4; y++)
            G[(ti*4+x)*65 + tj*4+y] = t1[x][y];
    __syncthreads();

    float cb[4][4] = {};
    for (int q = 0; q < 64; q++) {
        float a[4], bb[4];
#pragma unroll
        for (int x = 0; x < 4; x++) a[x]  = Vm[(ti*4+x)*65 + q];
#pragma unroll
        for (int y = 0; y < 4; y++) bb[y] = G[q*65 + tj*4+y];
#pragma unroll
        for (int x = 0; x < 4; x++)
#pragma unroll
            for (int y = 0; y < 4; y++)
                cb[x][y] = fmaf(a[x], bb[y], cb[x][y]);
    }
#pragma unroll
    for (int x = 0; x < 4; x++)
#pragma unroll
        for (int y = 0; y < 4; y++)
            CBV[(size_t)bh*4096 + (ti*4+x)*64 + tj*4+y] = cb[x][y];
}

// ---------------------------------------------------------------------------
// Y = A_hat @ CBV per head -> fp16 hi + lo (merged-head layout).
// ---------------------------------------------------------------------------
__global__ __launch_bounds__(256) void av_kernel(
    const float* __restrict__ Ahat, const float* __restrict__ CBV,
    __half* __restrict__ ahp, __half* __restrict__ alp)
{
    int bh = blockIdx.y;
    int b = bh >> 4, hh = bh & 15;
    int t0 = blockIdx.x * 64;
    __shared__ float As[64*65];
    __shared__ float Cs[64*65];
    int tid = threadIdx.x;
    for (int i = tid; i < 4096; i += 256) {
        int tl = i >> 6, c = i & 63;
        As[c*65 + tl] = Ahat[((size_t)bh*T_SEQ + t0 + tl)*64 + c];
        Cs[tl*65 + c] = CBV[(size_t)bh*4096 + i];
    }
    __syncthreads();
    int ti = tid >> 4, tj = tid & 15;
    float acc[4][4] = {};
    for (int c = 0; c < 64; c++) {
        float a[4], bb[4];
#pragma unroll
        for (int x = 0; x < 4; x++) a[x]  = As[c*65 + ti*4+x];
#pragma unroll
        for (int y = 0; y < 4; y++) bb[y] = Cs[c*65 + tj*4+y];
#pragma unroll
        for (int x = 0; x < 4; x++)
#pragma unroll
            for (int y = 0; y < 4; y++)
                acc[x][y] = fmaf(a[x], bb[y], acc[x][y]);
    }
#pragma unroll
    for (int x = 0; x < 4; x++) {
        size_t idx = ((size_t)b*T_SEQ + t0 + ti*4 + x)*DMODEL + hh*64 + tj*4;
#pragma unroll
        for (int y = 0; y < 4; y += 2) {
            float v0 = acc[x][y], v1 = acc[x][y+1];
            __half h0 = __float2half(v0);
            __half h1 = __float2half(v1);
            __half2 Hp, Lp;
            Hp.x = h0; Hp.y = h1;
            Lp.x = __float2half(v0 - __half2float(h0));
            Lp.y = __float2half(v1 - __half2float(h1));
            *(__half2*)(ahp + idx + y) = Hp;
            *(__half2*)(alp + idx + y) = Lp;
        }
    }
}

// ---------------------------------------------------------------------------
extern "C" void kernel_launch(void* const* d_in, const int* in_sizes, int n_in,
                              void* d_out, int out_size)
{
    (void)in_sizes; (void)n_in; (void)out_size;
    const float* x = (const float*)d_in[0];
    const float* Wq = (const float*)d_in[1];
    const float* Wk = (const float*)d_in[2];
    const float* Wv = (const float*)d_in[3];
    const float* Wo = (const float*)d_in[4];
    float* out = (float*)d_out;

    float *QKV, *A, *S, *Qlm, *Klm, *BV, *CBV, *BVp, *csump;
    __half *xh, *wh, *wl, *ah, *al;
    cudaGetSymbolAddress((void**)&QKV,   g_QKV);
    cudaGetSymbolAddress((void**)&A,     g_A);
    cudaGetSymbolAddress((void**)&S,     g_S);
    cudaGetSymbolAddress((void**)&Qlm,   g_Qlm);
    cudaGetSymbolAddress((void**)&Klm,   g_Klm);
    cudaGetSymbolAddress((void**)&BV,    g_BV);
    cudaGetSymbolAddress((void**)&CBV,   g_CBV);
    cudaGetSymbolAddress((void**)&BVp,   g_BVpart);
    cudaGetSymbolAddress((void**)&csump, g_csump);
    cudaGetSymbolAddress((void**)&xh,    g_xh);
    cudaGetSymbolAddress((void**)&wh,    g_wh);
    cudaGetSymbolAddress((void**)&wl,    g_wl);
    cudaGetSymbolAddress((void**)&ah,    g_ah);
    cudaGetSymbolAddress((void**)&al,    g_al);

    float* Q = QKV;
    float* K = QKV + (size_t)NROWS * DMODEL;
    float* V = QKV + 2 * (size_t)NROWS * DMODEL;

    cudaFuncSetAttribute(pinv_cbv_kernel,
                         cudaFuncAttributeMaxDynamicSharedMemorySize, 50432);
    cudaFuncSetAttribute(gemm_mma2_kernel,
                         cudaFuncAttributeMaxDynamicSharedMemorySize, G2_SMEM);
    cudaFuncSetAttribute(gemm_mma3_kernel,
                         cudaFuncAttributeMaxDynamicSharedMemorySize, G3_SMEM);

    // 3 launches before the GEMM so ncu -s 5 lands on the QKV GEMM
    wsplit4_kernel<<<dim3(1024, 4), 256>>>((const float4*)Wq, (const float4*)Wk,
        (const float4*)Wv, (const float4*)Wo, (__half2*)wh, (__half2*)wl);
    const int half4 = NROWS*DMODEL/8;
    xsplit_kernel<<<4096, 256>>>((const float4*)x, (__half2*)xh, half4);
    xsplit_kernel<<<4096, 256>>>((const float4*)x + half4,
        (__half2*)(xh + (size_t)NROWS*DMODEL/2), half4);

    // fused Q/K/V projection (2-term)
    dim3 gq(DMODEL/128, NROWS/128, 3);
    gemm_mma2_kernel<<<gq, 256, G2_SMEM>>>(xh, wh, wl, QKV,
                                           NROWS, DMODEL, DMODEL,
                                           (size_t)DMODEL*DMODEL, (size_t)NROWS*DMODEL);

    landmark_kernel<<<dim3(64, NBH, 2), 64>>>(Q, K, Qlm, Klm);
    scores_kernel<<<dim3(T_SEQ/128, NBH), 128>>>(Q, Klm, A, 1);
    scores_kernel<<<dim3(T_SEQ/128, NBH), 128>>>(K, Qlm, S, 0);
    bv_partial_kernel<<<dim3(8, NBH), 256>>>(S, V, BVp, csump);
    bv_reduce_kernel<<<NBH, 256>>>(BVp, csump, BV);
    pinv_cbv_kernel<<<NBH, 256, 50432>>>(Qlm, Klm, BV, CBV);
    av_kernel<<<dim3(T_SEQ/64, NBH), 256>>>(A, CBV, ah, al);

    // out projection (3-term: restores attn-quantization residual)
    dim3 go(DMODEL/128, NROWS/128);
    gemm_mma3_kernel<<<go, 256, G3_SMEM>>>(ah, al,
                                           wh + 3*(size_t)DMODEL*DMODEL,
                                           wl + 3*(size_t)DMODEL*DMODEL, out,
                                           NROWS, DMODEL, DMODEL);
}